// round 6
// baseline (speedup 1.0000x reference)
#include <cuda_runtime.h>
#include <cuda_bf16.h>
#include <math.h>
#include <stdint.h>

#define BB   16
#define TT   32
#define LL   64
#define DM   768
#define HH   12
#define HD   64
#define FF   2048
#define ZZ   100
#define NMAX 496
#define MROWS (NMAX * LL)

// ---------------- helpers ----------------
__device__ __forceinline__ uint32_t smem_u32(const void* p) {
    uint32_t a;
    asm("{ .reg .u64 t; cvta.to.shared.u64 t, %1; cvt.u32.u64 %0, t; }" : "=r"(a) : "l"(p));
    return a;
}
__device__ __forceinline__ void cp16(uint32_t dst, const void* src) {
    asm volatile("cp.async.cg.shared.global [%0], [%1], 16;" :: "r"(dst), "l"(src));
}
__device__ __forceinline__ void cp_commit() { asm volatile("cp.async.commit_group;" ::: "memory"); }
__device__ __forceinline__ void cp_wait0()  { asm volatile("cp.async.wait_group 0;" ::: "memory"); }
__device__ __forceinline__ void cp_wait1()  { asm volatile("cp.async.wait_group 1;" ::: "memory"); }
__device__ __forceinline__ void cp_wait2()  { asm volatile("cp.async.wait_group 2;" ::: "memory"); }
__device__ __forceinline__ void ldmx4(uint32_t& r0, uint32_t& r1, uint32_t& r2, uint32_t& r3,
                                      uint32_t addr) {
    asm volatile("ldmatrix.sync.aligned.m8n8.x4.shared.b16 {%0,%1,%2,%3}, [%4];"
                 : "=r"(r0), "=r"(r1), "=r"(r2), "=r"(r3) : "r"(addr));
}
__device__ __forceinline__ void ldmx4t(uint32_t& r0, uint32_t& r1, uint32_t& r2, uint32_t& r3,
                                       uint32_t addr) {
    asm volatile("ldmatrix.sync.aligned.m8n8.x4.trans.shared.b16 {%0,%1,%2,%3}, [%4];"
                 : "=r"(r0), "=r"(r1), "=r"(r2), "=r"(r3) : "r"(addr));
}
__device__ __forceinline__ void mma16816(float* c, const uint32_t* a, const uint32_t* b) {
    asm volatile("mma.sync.aligned.m16n8k16.row.col.f32.bf16.bf16.f32 "
                 "{%0,%1,%2,%3}, {%4,%5,%6,%7}, {%8,%9}, {%0,%1,%2,%3};"
                 : "+f"(c[0]), "+f"(c[1]), "+f"(c[2]), "+f"(c[3])
                 : "r"(a[0]), "r"(a[1]), "r"(a[2]), "r"(a[3]), "r"(b[0]), "r"(b[1]));
}
__device__ __forceinline__ int imin(int a, int b) { return a < b ? a : b; }

// fast exp on the FMA pipe; x <= 0 expected
__device__ __forceinline__ float fexp(float x) {
    float t = x * 1.44269504f;
    t = fmaxf(t, -125.0f);
    float e = floorf(t);
    float f = t - e;
    float p = 1.0f + f * (0.69314718f + f * (0.24022651f + f * (0.05550411f +
              f * (0.00961813f + f * 0.00133336f))));
    return p * __int_as_float(((int)e + 127) << 23);
}

// ---------------- device scratch ----------------
__device__ __nv_bfloat16 g_Xbf  [MROWS * DM];
__device__ __nv_bfloat16 g_QKVbf[MROWS * 3 * DM];
__device__ __nv_bfloat16 g_ATTbf[MROWS * DM];
__device__ __nv_bfloat16 g_Ybf  [MROWS * DM];
__device__ __nv_bfloat16 g_HIDbf[MROWS * FF];
__device__ __nv_bfloat16 g_Zbf  [MROWS * 128];

#define OFF_EQKV 0
#define SZ_QKV   (2 * 3 * DM * DM)
#define OFF_EOUT (OFF_EQKV + SZ_QKV)
#define SZ_OUT   (2 * DM * DM)
#define OFF_EW1  (OFF_EOUT + SZ_OUT)
#define SZ_W1    (2 * FF * DM)
#define OFF_EW2  (OFF_EW1 + SZ_W1)
#define SZ_W2    (2 * DM * FF)
#define OFF_DQKV (OFF_EW2 + SZ_W2)
#define OFF_DOUT (OFF_DQKV + SZ_QKV)
#define OFF_DW1  (OFF_DOUT + SZ_OUT)
#define OFF_DW2  (OFF_DW1 + SZ_W1)
#define OFF_PE   (OFF_DW2 + SZ_W2)
#define SZ_PE    (ZZ * DM)
#define OFF_PD   (OFF_PE + SZ_PE)
#define SZ_PD    (DM * 128)
#define WPOOL_SZ (OFF_PD + SZ_PD)
__device__ __nv_bfloat16 g_Wbf[WPOOL_SZ];

__device__ float g_MSK[NMAX * LL];
__device__ float g_meanE[NMAX * DM];
__device__ float g_s[NMAX];
__device__ int   g_Ntot;
__device__ int   g_nresp[BB];
__device__ int   g_next[BB];
__device__ int   g_bidx[NMAX];
__device__ int   g_tidx[NMAX];
__device__ int   g_nodefull[BB * TT];
__device__ int   g_oh[BB * TT];

// ---------------- setup / gather ----------------
__global__ void setup_kernel(const int* __restrict__ tree_lens) {
    if (threadIdx.x == 0 && blockIdx.x == 0) {
        int tot = 0;
        for (int b = 0; b < BB; b++) {
            int tl = tree_lens[b];
            int nr = tl - 1;
            g_nresp[b] = nr;
            int ne = (int)floor((double)nr * 0.05);
            if (ne < 1) ne = 1;
            g_next[b] = ne;
            for (int j = 1; j < tl; j++) { g_bidx[tot] = b; g_tidx[tot] = j; tot++; }
        }
        g_Ntot = tot;
    }
}

__global__ void gather_kernel(const float* __restrict__ emb, const float* __restrict__ amask) {
    int n = blockIdx.x, l = blockIdx.y;
    if (n >= g_Ntot) return;
    int bi = g_bidx[n], ti = g_tidx[n];
    const float* src = emb + (((size_t)bi * TT + ti) * LL + l) * DM;
    __nv_bfloat16* dst = g_Xbf + ((size_t)n * LL + l) * DM;
    for (int d = threadIdx.x; d < DM; d += blockDim.x) dst[d] = __float2bfloat16(src[d]);
    if (threadIdx.x == 0)
        g_MSK[n * LL + l] = amask[((size_t)bi * TT + ti) * LL + l];
}

__global__ void meanE_kernel(const float* __restrict__ emb) {
    int n = blockIdx.x;
    if (n >= g_Ntot) return;
    int d = blockIdx.y * 256 + threadIdx.x;
    int bi = g_bidx[n], ti = g_tidx[n];
    const float* base = emb + ((size_t)bi * TT + ti) * LL * DM;
    float s = 0.f;
    for (int l = 0; l < LL; l++) s += base[(size_t)l * DM + d];
    g_meanE[n * DM + d] = s * (1.f / (float)LL);
}

// ---------------- weight converts (vectorized) ----------------
__global__ void conv_kernel(const float4* __restrict__ src, __nv_bfloat162* __restrict__ dst,
                            int cnt4) {
    for (int i = blockIdx.x * blockDim.x + threadIdx.x; i < cnt4; i += gridDim.x * blockDim.x) {
        float4 v = src[i];
        dst[2 * i]     = __floats2bfloat162_rn(v.x, v.y);
        dst[2 * i + 1] = __floats2bfloat162_rn(v.z, v.w);
    }
}
__global__ void conv_pad_kernel(const float* __restrict__ src, __nv_bfloat16* __restrict__ dst) {
    int i = blockIdx.x * blockDim.x + threadIdx.x;
    if (i >= DM * 128) return;
    int r = i >> 7, c = i & 127;
    dst[i] = __float2bfloat16((c < ZZ) ? src[r * ZZ + c] : 0.f);
}

// ---------------- warp-MMA GEMM: 256x128x32 block, 8 warps, warp tile 64x64 ----------------
// 4-slot cp.async pipeline, depth 3, one __syncthreads per k-tile.
// C[M,N] = A[M,K] @ B[N,K]^T (+bias, act). MODE: 0 none / 1 relu / 2 tanh
#define MM_SMEM ((4 * 256 * 40 + 4 * 128 * 40) * 2)

template <int MODE>
__global__ void __launch_bounds__(256) mm_kernel(
    const __nv_bfloat16* __restrict__ A, long long sAi,
    const __nv_bfloat16* __restrict__ B, long long sBi,
    const float* __restrict__ bias,
    __nv_bfloat16* __restrict__ C, long long sCi,
    int Nreal, int Kdim)
{
    int Mreal = g_Ntot * LL;
    int m0 = blockIdx.y * 256;
    if (m0 >= Mreal) return;
    int n0 = blockIdx.x * 128;
    size_t stA = (size_t)sAi, stB = (size_t)sBi;
    int Ktiles = Kdim >> 5;

    extern __shared__ __nv_bfloat16 sm[];
    __nv_bfloat16* As = sm;                    // [4][256][40]
    __nv_bfloat16* Bs = sm + 4 * 256 * 40;     // [4][128][40]

    int tid = threadIdx.x;
    int lane = tid & 31;
    int w = tid >> 5;
    int wm = w >> 1;   // 0..3 (64 rows each)
    int wn = w & 1;    // 0..1 (64 cols each)

    float acc[4][8][4];
#pragma unroll
    for (int i = 0; i < 4; i++)
#pragma unroll
        for (int j = 0; j < 8; j++)
#pragma unroll
            for (int q = 0; q < 4; q++) acc[i][j][q] = 0.f;

    auto load_tile = [&](int kt, int s) {
        __nv_bfloat16* as = As + s * 256 * 40;
        __nv_bfloat16* bs = Bs + s * 128 * 40;
#pragma unroll
        for (int i = 0; i < 4; i++) {
            int c = tid + i * 256;
            int r = c >> 2, ko = (c & 3) * 8;
            int m = imin(m0 + r, Mreal - 1);
            cp16(smem_u32(&as[r * 40 + ko]), A + (size_t)m * stA + (size_t)kt * 32 + ko);
        }
#pragma unroll
        for (int i = 0; i < 2; i++) {
            int c = tid + i * 256;
            int r = c >> 2, ko = (c & 3) * 8;
            int n = imin(n0 + r, Nreal - 1);
            cp16(smem_u32(&bs[r * 40 + ko]), B + (size_t)n * stB + (size_t)kt * 32 + ko);
        }
    };

    load_tile(0, 0); cp_commit();
    if (Ktiles > 1) load_tile(1, 1);
    cp_commit();

    for (int kt = 0; kt < Ktiles; kt++) {
        if (kt + 2 < Ktiles) load_tile(kt + 2, (kt + 2) & 3);
        cp_commit();
        cp_wait2();
        __syncthreads();

        int s = kt & 3;
        const __nv_bfloat16* as = As + s * 256 * 40;
        const __nv_bfloat16* bs = Bs + s * 128 * 40;
#pragma unroll
        for (int ks = 0; ks < 2; ks++) {
            int k0 = ks * 16;
            uint32_t a[4][4], bb[8][2];
#pragma unroll
            for (int mf = 0; mf < 4; mf++) {
                int row = wm * 64 + mf * 16 + (lane & 7) + ((lane >> 3) & 1) * 8;
                int col = k0 + (lane >> 4) * 8;
                ldmx4(a[mf][0], a[mf][1], a[mf][2], a[mf][3], smem_u32(&as[row * 40 + col]));
            }
#pragma unroll
            for (int ng = 0; ng < 4; ng++) {
                int row = wn * 64 + ng * 16 + (lane & 7) + (lane >> 4) * 8;
                int col = k0 + ((lane >> 3) & 1) * 8;
                uint32_t r0, r1, r2, r3;
                ldmx4(r0, r1, r2, r3, smem_u32(&bs[row * 40 + col]));
                bb[ng * 2][0] = r0;     bb[ng * 2][1] = r1;
                bb[ng * 2 + 1][0] = r2; bb[ng * 2 + 1][1] = r3;
            }
#pragma unroll
            for (int mf = 0; mf < 4; mf++)
#pragma unroll
                for (int nf = 0; nf < 8; nf++)
                    mma16816(acc[mf][nf], a[mf], bb[nf]);
        }
    }

    int width = (int)sCi;
#pragma unroll
    for (int mf = 0; mf < 4; mf++) {
#pragma unroll
        for (int nf = 0; nf < 8; nf++) {
            int rbase = m0 + wm * 64 + mf * 16 + (lane >> 2);
            int cbase = n0 + wn * 64 + nf * 8 + (lane & 3) * 2;
            if (cbase >= width) continue;
#pragma unroll
            for (int q = 0; q < 2; q++) {
                int m = rbase + q * 8;
                if (m >= Mreal) continue;
                float v0 = (cbase < Nreal)     ? acc[mf][nf][q * 2]     + bias[cbase]     : 0.f;
                float v1 = (cbase + 1 < Nreal) ? acc[mf][nf][q * 2 + 1] + bias[cbase + 1] : 0.f;
                if (MODE == 1) { v0 = fmaxf(v0, 0.f); v1 = fmaxf(v1, 0.f); }
                if (MODE == 2) { v0 = tanhf(v0); v1 = tanhf(v1); }
                *(__nv_bfloat162*)(C + (size_t)m * width + cbase) = __floats2bfloat162_rn(v0, v1);
            }
        }
    }
}

// ---------------- fused attention (unchanged from round 5) ----------------
#define SP_STRIDE 520
#define SM_SP  0
#define SM_Q   (64 * SP_STRIDE * 2)
#define SM_KV  (SM_Q + 64 * 72 * 2)
#define SM_MSK (SM_KV + 2 * 64 * 72 * 2)
#define ATTN_SMEM (SM_MSK + 512 * 4)

__global__ void __launch_bounds__(256) attn_kernel(
    const __nv_bfloat16* __restrict__ QKV, __nv_bfloat16* __restrict__ ATT)
{
    int Nt = g_Ntot;
    int n0 = blockIdx.x * 64;
    if (n0 >= Nt) return;
    int z = blockIdx.y;
    int l = z / HH, h = z % HH;
    int Kc = (Nt + 63) & ~63;
    int Mtiles = Kc >> 6;

    extern __shared__ char smem[];
    __nv_bfloat16* SP = (__nv_bfloat16*)(smem + SM_SP);
    __nv_bfloat16* Qs = (__nv_bfloat16*)(smem + SM_Q);
    __nv_bfloat16* KV = (__nv_bfloat16*)(smem + SM_KV);
    float*        msk = (float*)(smem + SM_MSK);

    int tid = threadIdx.x;
    int lane = tid & 31;
    int w = tid >> 5;
    int wm = w >> 1;
    int wn = w & 1;

    for (int j = tid; j < 512; j += 256)
        msk[j] = (j < Nt) ? g_MSK[j * LL + l] : -1e30f;

#pragma unroll
    for (int i = 0; i < 2; i++) {
        int c = tid + i * 256;
        int r = c >> 3, co = (c & 7) * 8;
        int n = imin(n0 + r, Nt - 1);
        cp16(smem_u32(&Qs[r * 72 + co]), QKV + ((size_t)n * LL + l) * (3 * DM) + h * HD + co);
    }

    auto load_kv = [&](int mt, int buf, int which) {
#pragma unroll
        for (int i = 0; i < 2; i++) {
            int c = tid + i * 256;
            int r = c >> 3, co = (c & 7) * 8;
            int m = imin(mt * 64 + r, Nt - 1);
            cp16(smem_u32(&KV[(buf * 64 + r) * 72 + co]),
                 QKV + ((size_t)m * LL + l) * (3 * DM) + which * DM + h * HD + co);
        }
    };

    load_kv(0, 0, 1);
    cp_commit();

    for (int mt = 0; mt < Mtiles; mt++) {
        int buf = mt & 1;
        if (mt + 1 < Mtiles) { load_kv(mt + 1, buf ^ 1, 1); cp_commit(); cp_wait1(); }
        else cp_wait0();
        __syncthreads();

        float acc[4][4];
#pragma unroll
        for (int j = 0; j < 4; j++)
#pragma unroll
            for (int q = 0; q < 4; q++) acc[j][q] = 0.f;

#pragma unroll
        for (int ks = 0; ks < 4; ks++) {
            int k0 = ks * 16;
            uint32_t a[4], bb[4][2];
            {
                int row = wm * 16 + (lane & 7) + ((lane >> 3) & 1) * 8;
                int col = k0 + (lane >> 4) * 8;
                ldmx4(a[0], a[1], a[2], a[3], smem_u32(&Qs[row * 72 + col]));
            }
#pragma unroll
            for (int ng = 0; ng < 2; ng++) {
                int row = wn * 32 + ng * 16 + (lane & 7) + (lane >> 4) * 8;
                int col = k0 + ((lane >> 3) & 1) * 8;
                uint32_t r0, r1, r2, r3;
                ldmx4(r0, r1, r2, r3, smem_u32(&KV[(buf * 64 + row) * 72 + col]));
                bb[ng * 2][0] = r0;     bb[ng * 2][1] = r1;
                bb[ng * 2 + 1][0] = r2; bb[ng * 2 + 1][1] = r3;
            }
#pragma unroll
            for (int nf = 0; nf < 4; nf++) mma16816(acc[nf], a, bb[nf]);
        }
        int rbase = wm * 16 + (lane >> 2);
#pragma unroll
        for (int nf = 0; nf < 4; nf++) {
            int cl = wn * 32 + nf * 8 + (lane & 3) * 2;
            int gc = mt * 64 + cl;
            float m0v = msk[gc], m1v = msk[gc + 1];
#pragma unroll
            for (int q = 0; q < 2; q++) {
                int r = rbase + q * 8;
                float v0 = acc[nf][q * 2]     * 0.125f + m0v;
                float v1 = acc[nf][q * 2 + 1] * 0.125f + m1v;
                *(__nv_bfloat162*)&SP[r * SP_STRIDE + gc] = __floats2bfloat162_rn(v0, v1);
            }
        }
        __syncthreads();
    }

    {
        int cnt = Kc >> 5;
        for (int rr = 0; rr < 8; rr++) {
            int r = w * 8 + rr;
            float vals[16];
            float mx = -INFINITY;
            for (int i = 0; i < cnt; i++) {
                vals[i] = __bfloat162float(SP[r * SP_STRIDE + lane + i * 32]);
                mx = fmaxf(mx, vals[i]);
            }
#pragma unroll
            for (int o = 16; o > 0; o >>= 1) mx = fmaxf(mx, __shfl_xor_sync(0xffffffff, mx, o));
            float sum = 0.f;
            for (int i = 0; i < cnt; i++) { vals[i] = fexp(vals[i] - mx); sum += vals[i]; }
#pragma unroll
            for (int o = 16; o > 0; o >>= 1) sum += __shfl_xor_sync(0xffffffff, sum, o);
            float inv = 1.f / sum;
            for (int i = 0; i < cnt; i++)
                SP[r * SP_STRIDE + lane + i * 32] = __float2bfloat16(vals[i] * inv);
        }
    }
    __syncthreads();

    float oacc[4][4];
#pragma unroll
    for (int j = 0; j < 4; j++)
#pragma unroll
        for (int q = 0; q < 4; q++) oacc[j][q] = 0.f;

    load_kv(0, 0, 2);
    cp_commit();

    for (int mt = 0; mt < Mtiles; mt++) {
        int buf = mt & 1;
        if (mt + 1 < Mtiles) { load_kv(mt + 1, buf ^ 1, 2); cp_commit(); cp_wait1(); }
        else cp_wait0();
        __syncthreads();

#pragma unroll
        for (int ks = 0; ks < 4; ks++) {
            int mk0 = mt * 64 + ks * 16;
            uint32_t a[4], bb[4][2];
            {
                int row = wm * 16 + (lane & 7) + ((lane >> 3) & 1) * 8;
                int col = mk0 + (lane >> 4) * 8;
                ldmx4(a[0], a[1], a[2], a[3], smem_u32(&SP[row * SP_STRIDE + col]));
            }
#pragma unroll
            for (int ng = 0; ng < 2; ng++) {
                int vrow = ks * 16 + (lane & 7) + ((lane >> 3) & 1) * 8;
                int vcol = wn * 32 + ng * 16 + (lane >> 4) * 8;
                uint32_t r0, r1, r2, r3;
                ldmx4t(r0, r1, r2, r3, smem_u32(&KV[(buf * 64 + vrow) * 72 + vcol]));
                bb[ng * 2][0] = r0;     bb[ng * 2][1] = r1;
                bb[ng * 2 + 1][0] = r2; bb[ng * 2 + 1][1] = r3;
            }
#pragma unroll
            for (int nf = 0; nf < 4; nf++) mma16816(oacc[nf], a, bb[nf]);
        }
        __syncthreads();
    }

    int rbase = wm * 16 + (lane >> 2);
#pragma unroll
    for (int nf = 0; nf < 4; nf++) {
        int c = wn * 32 + nf * 8 + (lane & 3) * 2;
#pragma unroll
        for (int q = 0; q < 2; q++) {
            int n = n0 + rbase + q * 8;
            if (n < Nt) {
                __nv_bfloat16* row = ATT + ((size_t)n * LL + l) * DM + h * HD + c;
                *(__nv_bfloat162*)row =
                    __floats2bfloat162_rn(oacc[nf][q * 2], oacc[nf][q * 2 + 1]);
            }
        }
    }
}

// ---------------- residual + LayerNorm ----------------
__global__ void add_ln_kernel(__nv_bfloat16* __restrict__ X, const __nv_bfloat16* __restrict__ Yv,
                              const float* __restrict__ g, const float* __restrict__ b) {
    int row = blockIdx.x;
    if (row >= g_Ntot * LL) return;
    __nv_bfloat16* x = X + (size_t)row * DM;
    const __nv_bfloat16* y = Yv + (size_t)row * DM;
    int t = threadIdx.x;
    float v[3], s = 0.f, s2 = 0.f;
#pragma unroll
    for (int i = 0; i < 3; i++) {
        int d = t + 256 * i;
        float u = __bfloat162float(x[d]) + __bfloat162float(y[d]);
        v[i] = u; s += u; s2 += u * u;
    }
    __shared__ float rs[256], rs2[256];
    rs[t] = s; rs2[t] = s2; __syncthreads();
    for (int st = 128; st > 0; st >>= 1) {
        if (t < st) { rs[t] += rs[t + st]; rs2[t] += rs2[t + st]; }
        __syncthreads();
    }
    float mean = rs[0] * (1.f / (float)DM);
    float var = rs2[0] * (1.f / (float)DM) - mean * mean;
    float inv = rsqrtf(var + 1e-5f);
#pragma unroll
    for (int i = 0; i < 3; i++) {
        int d = t + 256 * i;
        x[d] = __float2bfloat16((v[i] - mean) * inv * g[d] + b[d]);
    }
}

// ---------------- anomaly ----------------
__global__ void anomaly_kernel() {
    int n = blockIdx.x;
    if (n >= g_Ntot) return;
    int t = threadIdx.x;
    float acc = 0.f;
#pragma unroll
    for (int i = 0; i < 3; i++) {
        int d = t + 256 * i;
        float m = 0.f;
        for (int l = 0; l < LL; l++)
            m += __bfloat162float(g_Xbf[((size_t)n * LL + l) * DM + d]);
        m *= (1.f / (float)LL);
        float diff = m - g_meanE[n * DM + d];
        acc += diff * diff;
    }
    __shared__ float red[256];
    red[t] = acc; __syncthreads();
    for (int s = 128; s > 0; s >>= 1) { if (t < s) red[t] += red[t + s]; __syncthreads(); }
    if (t == 0) g_s[n] = red[0];
}

// ---------------- selection ----------------
__global__ void select_kernel() {
    int b = threadIdx.x;
    if (b >= BB) return;
    int nr = g_nresp[b];
    int ne = g_next[b];
    bool used[TT];
    int ohf[TT];
#pragma unroll
    for (int j = 0; j < TT; j++) { used[j] = false; ohf[j] = 0; }
    ohf[0] = 1;
    g_nodefull[b * TT + 0] = 0;
    for (int i = 0; i < TT - 1; i++) {
        int node = 0;
        if (i < ne) {
            float best = INFINITY; int bj = 0;
            for (int j = 0; j < nr; j++) {
                if (!used[j] && g_s[j] < best) { best = g_s[j]; bj = j; }
            }
            used[bj] = true;
            node = bj + 1;
            ohf[node] = 1;
        }
        g_nodefull[b * TT + i + 1] = node;
    }
    for (int t = 0; t < TT; t++) g_oh[b * TT + t] = ohf[t];
}

// ---------------- output writers ----------------
__global__ void out_small_kernel(float* __restrict__ out, long long off_oh,
                                 long long off_sc, long long off_tl, int has_sc) {
    int t = blockIdx.x * blockDim.x + threadIdx.x;
    if (t < BB * TT) out[off_oh + t] = (float)g_oh[t];
    else if (t < BB * TT + BB) out[off_tl + (t - BB * TT)] = (float)(1 + g_next[t - BB * TT]);
    else if (t == BB * TT + BB && has_sc) out[off_sc] = 0.f;
}
__global__ void ext_mask_kernel(float* __restrict__ out, long long off) {
    int bt = blockIdx.x;
    out[off + (size_t)bt * LL + threadIdx.x] = (float)g_oh[bt];
}
__global__ void new_msk_kernel(const float* __restrict__ amask,
                               float* __restrict__ out, long long off) {
    int bt = blockIdx.x;
    int b = bt >> 5, t = bt & 31;
    int node = g_nodefull[bt];
    float valid = (t == 0 || (t - 1) < g_next[b]) ? 1.f : 0.f;
    out[off + (size_t)bt * LL + threadIdx.x] =
        amask[((size_t)b * TT + node) * LL + threadIdx.x] * valid;
}
__global__ void new_emb_kernel(const float* __restrict__ emb,
                               float* __restrict__ out, long long off) {
    int bt = blockIdx.x / 192;
    int r = (blockIdx.x % 192) * 256 + threadIdx.x;
    int b = bt >> 5;
    int node = g_nodefull[bt];
    out[off + (size_t)bt * (LL * DM) + r] =
        emb[((size_t)b * TT + node) * (LL * DM) + r];
}

// ---------------- host ----------------
static void run_layer(__nv_bfloat16* pW, int qkvOff, int outOff, int w1Off, int w2Off,
                      const float* qkvb, const float* outb,
                      const float* g1, const float* b1,
                      const float* c1, const float* c2,
                      const float* g2, const float* b2,
                      __nv_bfloat16* pX, __nv_bfloat16* pQKV, __nv_bfloat16* pATT,
                      __nv_bfloat16* pY, __nv_bfloat16* pHID) {
    const int GY = 124;  // ceil(NMAX*64 / 256)
    mm_kernel<0><<<dim3(18, GY), 256, MM_SMEM>>>(pX, DM, pW + qkvOff, DM, qkvb, pQKV, 3 * DM, 3 * DM, DM);
    attn_kernel<<<dim3(8, 768), 256, ATTN_SMEM>>>(pQKV, pATT);
    mm_kernel<0><<<dim3(6, GY), 256, MM_SMEM>>>(pATT, DM, pW + outOff, DM, outb, pY, DM, DM, DM);
    add_ln_kernel<<<NMAX * LL, 256>>>(pX, pY, g1, b1);
    mm_kernel<1><<<dim3(16, GY), 256, MM_SMEM>>>(pX, DM, pW + w1Off, DM, c1, pHID, FF, FF, DM);
    mm_kernel<0><<<dim3(6, GY), 256, MM_SMEM>>>(pHID, FF, pW + w2Off, FF, c2, pY, DM, DM, FF);
    add_ln_kernel<<<NMAX * LL, 256>>>(pX, pY, g2, b2);
}

extern "C" void kernel_launch(void* const* d_in, const int* in_sizes, int n_in,
                              void* d_out, int out_size) {
    const int*   tree_lens = (const int*)d_in[0];
    const float* emb       = (const float*)d_in[1];
    const float* amask     = (const float*)d_in[2];
    const float* P[28];
    for (int i = 3; i < 31; i++) P[i - 3] = (const float*)d_in[i];
    float* out = (float*)d_out;

    __nv_bfloat16 *pX, *pQKV, *pATT, *pY, *pHID, *pZ, *pW;
    cudaGetSymbolAddress((void**)&pX, g_Xbf);
    cudaGetSymbolAddress((void**)&pQKV, g_QKVbf);
    cudaGetSymbolAddress((void**)&pATT, g_ATTbf);
    cudaGetSymbolAddress((void**)&pY, g_Ybf);
    cudaGetSymbolAddress((void**)&pHID, g_HIDbf);
    cudaGetSymbolAddress((void**)&pZ, g_Zbf);
    cudaGetSymbolAddress((void**)&pW, g_Wbf);

    cudaFuncSetAttribute(attn_kernel, cudaFuncAttributeMaxDynamicSharedMemorySize, ATTN_SMEM);
    cudaFuncSetAttribute(mm_kernel<0>, cudaFuncAttributeMaxDynamicSharedMemorySize, MM_SMEM);
    cudaFuncSetAttribute(mm_kernel<1>, cudaFuncAttributeMaxDynamicSharedMemorySize, MM_SMEM);
    cudaFuncSetAttribute(mm_kernel<2>, cudaFuncAttributeMaxDynamicSharedMemorySize, MM_SMEM);

    const long long NE_ELEMS = (long long)BB * TT * LL * DM;
    const long long TOT_W = 512 + 32768 + 1 + 16 + NE_ELEMS + 32768;
    int has_sc = ((long long)out_size == TOT_W - 1) ? 0 : 1;
    long long off_oh = 0;
    long long off_em = 512;
    long long off_sc = 512 + 32768;
    long long off_tl = off_sc + (has_sc ? 1 : 0);
    long long off_ne = off_tl + 16;
    long long off_nm = off_ne + NE_ELEMS;

    setup_kernel<<<1, 32>>>(tree_lens);
    gather_kernel<<<dim3(NMAX, LL), 256>>>(emb, amask);
    meanE_kernel<<<dim3(NMAX, 3), 256>>>(emb);

    conv_kernel<<<1024, 256>>>((const float4*)P[0],  (__nv_bfloat162*)(pW + OFF_EQKV), SZ_QKV / 4);
    conv_kernel<<<1024, 256>>>((const float4*)P[2],  (__nv_bfloat162*)(pW + OFF_EOUT), SZ_OUT / 4);
    conv_kernel<<<1024, 256>>>((const float4*)P[6],  (__nv_bfloat162*)(pW + OFF_EW1),  SZ_W1 / 4);
    conv_kernel<<<1024, 256>>>((const float4*)P[8],  (__nv_bfloat162*)(pW + OFF_EW2),  SZ_W2 / 4);
    conv_kernel<<<1024, 256>>>((const float4*)P[12], (__nv_bfloat162*)(pW + OFF_DQKV), SZ_QKV / 4);
    conv_kernel<<<1024, 256>>>((const float4*)P[14], (__nv_bfloat162*)(pW + OFF_DOUT), SZ_OUT / 4);
    conv_kernel<<<1024, 256>>>((const float4*)P[18], (__nv_bfloat162*)(pW + OFF_DW1),  SZ_W1 / 4);
    conv_kernel<<<1024, 256>>>((const float4*)P[20], (__nv_bfloat162*)(pW + OFF_DW2),  SZ_W2 / 4);
    conv_kernel<<<128, 256>>>((const float4*)P[24],  (__nv_bfloat162*)(pW + OFF_PE),   SZ_PE / 4);
    conv_pad_kernel<<<(DM * 128 + 255) / 256, 256>>>(P[26], pW + OFF_PD);

    const int LQKV = 3 * DM * DM, LOUT = DM * DM, LW1 = FF * DM, LW2 = DM * FF;
    for (int i = 0; i < 2; i++)
        run_layer(pW, OFF_EQKV + i * LQKV, OFF_EOUT + i * LOUT,
                  OFF_EW1 + i * LW1, OFF_EW2 + i * LW2,
                  P[1] + (size_t)i * 3 * DM, P[3] + (size_t)i * DM,
                  P[4] + (size_t)i * DM, P[5] + (size_t)i * DM,
                  P[7] + (size_t)i * FF, P[9] + (size_t)i * DM,
                  P[10] + (size_t)i * DM, P[11] + (size_t)i * DM,
                  pX, pQKV, pATT, pY, pHID);

    mm_kernel<2><<<dim3(1, 124), 256, MM_SMEM>>>(pX, DM, pW + OFF_PE, DM, P[25], pZ, 128, ZZ, DM);
    mm_kernel<2><<<dim3(6, 124), 256, MM_SMEM>>>(pZ, 128, pW + OFF_PD, 128, P[27], pX, DM, DM, 128);

    for (int i = 0; i < 2; i++)
        run_layer(pW, OFF_DQKV + i * LQKV, OFF_DOUT + i * LOUT,
                  OFF_DW1 + i * LW1, OFF_DW2 + i * LW2,
                  P[13] + (size_t)i * 3 * DM, P[15] + (size_t)i * DM,
                  P[16] + (size_t)i * DM, P[17] + (size_t)i * DM,
                  P[19] + (size_t)i * FF, P[21] + (size_t)i * DM,
                  P[22] + (size_t)i * DM, P[23] + (size_t)i * DM,
                  pX, pQKV, pATT, pY, pHID);

    anomaly_kernel<<<NMAX, 256>>>();
    select_kernel<<<1, 32>>>();

    out_small_kernel<<<3, 256>>>(out, off_oh, off_sc, off_tl, has_sc);
    ext_mask_kernel<<<BB * TT, LL>>>(out, off_em);
    new_msk_kernel<<<BB * TT, LL>>>(amask, out, off_nm);
    new_emb_kernel<<<BB * TT * 192, 256>>>(emb, out, off_ne);
}

// round 7
// speedup vs baseline: 1.1440x; 1.1440x over previous
#include <cuda_runtime.h>
#include <cuda_bf16.h>
#include <math.h>
#include <stdint.h>

#define BB   16
#define TT   32
#define LL   64
#define DM   768
#define HH   12
#define HD   64
#define FF   2048
#define ZZ   100
#define NMAX 496
#define MROWS (NMAX * LL)

// ---------------- helpers ----------------
__device__ __forceinline__ uint32_t smem_u32(const void* p) {
    uint32_t a;
    asm("{ .reg .u64 t; cvta.to.shared.u64 t, %1; cvt.u32.u64 %0, t; }" : "=r"(a) : "l"(p));
    return a;
}
__device__ __forceinline__ void cp16(uint32_t dst, const void* src) {
    asm volatile("cp.async.cg.shared.global [%0], [%1], 16;" :: "r"(dst), "l"(src));
}
__device__ __forceinline__ void cp_commit() { asm volatile("cp.async.commit_group;" ::: "memory"); }
__device__ __forceinline__ void cp_wait0()  { asm volatile("cp.async.wait_group 0;" ::: "memory"); }
__device__ __forceinline__ void cp_wait1()  { asm volatile("cp.async.wait_group 1;" ::: "memory"); }
__device__ __forceinline__ void cp_wait2()  { asm volatile("cp.async.wait_group 2;" ::: "memory"); }
__device__ __forceinline__ void ldmx4(uint32_t& r0, uint32_t& r1, uint32_t& r2, uint32_t& r3,
                                      uint32_t addr) {
    asm volatile("ldmatrix.sync.aligned.m8n8.x4.shared.b16 {%0,%1,%2,%3}, [%4];"
                 : "=r"(r0), "=r"(r1), "=r"(r2), "=r"(r3) : "r"(addr));
}
__device__ __forceinline__ void ldmx4t(uint32_t& r0, uint32_t& r1, uint32_t& r2, uint32_t& r3,
                                       uint32_t addr) {
    asm volatile("ldmatrix.sync.aligned.m8n8.x4.trans.shared.b16 {%0,%1,%2,%3}, [%4];"
                 : "=r"(r0), "=r"(r1), "=r"(r2), "=r"(r3) : "r"(addr));
}
__device__ __forceinline__ void mma16816(float* c, const uint32_t* a, const uint32_t* b) {
    asm volatile("mma.sync.aligned.m16n8k16.row.col.f32.bf16.bf16.f32 "
                 "{%0,%1,%2,%3}, {%4,%5,%6,%7}, {%8,%9}, {%0,%1,%2,%3};"
                 : "+f"(c[0]), "+f"(c[1]), "+f"(c[2]), "+f"(c[3])
                 : "r"(a[0]), "r"(a[1]), "r"(a[2]), "r"(a[3]), "r"(b[0]), "r"(b[1]));
}
__device__ __forceinline__ int imin(int a, int b) { return a < b ? a : b; }

// fast exp on the FMA pipe; x <= 0 expected
__device__ __forceinline__ float fexp(float x) {
    float t = x * 1.44269504f;
    t = fmaxf(t, -125.0f);
    float e = floorf(t);
    float f = t - e;
    float p = 1.0f + f * (0.69314718f + f * (0.24022651f + f * (0.05550411f +
              f * (0.00961813f + f * 0.00133336f))));
    return p * __int_as_float(((int)e + 127) << 23);
}

// ---------------- device scratch ----------------
__device__ __nv_bfloat16 g_Xbf  [MROWS * DM];
__device__ __nv_bfloat16 g_QKVbf[MROWS * 3 * DM];
__device__ __nv_bfloat16 g_ATTbf[MROWS * DM];
__device__ __nv_bfloat16 g_Ybf  [MROWS * DM];
__device__ __nv_bfloat16 g_HIDbf[MROWS * FF];
__device__ __nv_bfloat16 g_Zbf  [MROWS * 128];

#define OFF_EQKV 0
#define SZ_QKV   (2 * 3 * DM * DM)
#define OFF_EOUT (OFF_EQKV + SZ_QKV)
#define SZ_OUT   (2 * DM * DM)
#define OFF_EW1  (OFF_EOUT + SZ_OUT)
#define SZ_W1    (2 * FF * DM)
#define OFF_EW2  (OFF_EW1 + SZ_W1)
#define SZ_W2    (2 * DM * FF)
#define OFF_DQKV (OFF_EW2 + SZ_W2)
#define OFF_DOUT (OFF_DQKV + SZ_QKV)
#define OFF_DW1  (OFF_DOUT + SZ_OUT)
#define OFF_DW2  (OFF_DW1 + SZ_W1)
#define OFF_PE   (OFF_DW2 + SZ_W2)
#define SZ_PE    (ZZ * DM)
#define OFF_PD   (OFF_PE + SZ_PE)
#define SZ_PD    (DM * 128)
#define WPOOL_SZ (OFF_PD + SZ_PD)
__device__ __nv_bfloat16 g_Wbf[WPOOL_SZ];

__device__ float g_MSK[NMAX * LL];
__device__ float g_meanE[NMAX * DM];
__device__ float g_s[NMAX];
__device__ int   g_Ntot;
__device__ int   g_nresp[BB];
__device__ int   g_next[BB];
__device__ int   g_bidx[NMAX];
__device__ int   g_tidx[NMAX];
__device__ int   g_nodefull[BB * TT];
__device__ int   g_oh[BB * TT];

// ---------------- setup / gather ----------------
__global__ void setup_kernel(const int* __restrict__ tree_lens) {
    if (threadIdx.x == 0 && blockIdx.x == 0) {
        int tot = 0;
        for (int b = 0; b < BB; b++) {
            int tl = tree_lens[b];
            int nr = tl - 1;
            g_nresp[b] = nr;
            int ne = (int)floor((double)nr * 0.05);
            if (ne < 1) ne = 1;
            g_next[b] = ne;
            for (int j = 1; j < tl; j++) { g_bidx[tot] = b; g_tidx[tot] = j; tot++; }
        }
        g_Ntot = tot;
    }
}

__global__ void gather_kernel(const float* __restrict__ emb, const float* __restrict__ amask) {
    int n = blockIdx.x, l = blockIdx.y;
    if (n >= g_Ntot) return;
    int bi = g_bidx[n], ti = g_tidx[n];
    const float* src = emb + (((size_t)bi * TT + ti) * LL + l) * DM;
    __nv_bfloat16* dst = g_Xbf + ((size_t)n * LL + l) * DM;
    for (int d = threadIdx.x; d < DM; d += blockDim.x) dst[d] = __float2bfloat16(src[d]);
    if (threadIdx.x == 0)
        g_MSK[n * LL + l] = amask[((size_t)bi * TT + ti) * LL + l];
}

__global__ void meanE_kernel(const float* __restrict__ emb) {
    int n = blockIdx.x;
    if (n >= g_Ntot) return;
    int d = blockIdx.y * 256 + threadIdx.x;
    int bi = g_bidx[n], ti = g_tidx[n];
    const float* base = emb + ((size_t)bi * TT + ti) * LL * DM;
    float s = 0.f;
    for (int l = 0; l < LL; l++) s += base[(size_t)l * DM + d];
    g_meanE[n * DM + d] = s * (1.f / (float)LL);
}

// ---------------- weight converts (vectorized) ----------------
__global__ void conv_kernel(const float4* __restrict__ src, __nv_bfloat162* __restrict__ dst,
                            int cnt4) {
    for (int i = blockIdx.x * blockDim.x + threadIdx.x; i < cnt4; i += gridDim.x * blockDim.x) {
        float4 v = src[i];
        dst[2 * i]     = __floats2bfloat162_rn(v.x, v.y);
        dst[2 * i + 1] = __floats2bfloat162_rn(v.z, v.w);
    }
}
__global__ void conv_pad_kernel(const float* __restrict__ src, __nv_bfloat16* __restrict__ dst) {
    int i = blockIdx.x * blockDim.x + threadIdx.x;
    if (i >= DM * 128) return;
    int r = i >> 7, c = i & 127;
    dst[i] = __float2bfloat16((c < ZZ) ? src[r * ZZ + c] : 0.f);
}

// ---------------- warp-MMA GEMM: 128x128x32 block, 8 warps, warp tile 32x64 ----------------
// 4-slot cp.async pipeline, depth 3, ONE __syncthreads per k-tile, 2 CTAs/SM.
// C[M,N] = A[M,K] @ B[N,K]^T (+bias, act). MODE: 0 none / 1 relu / 2 tanh
#define MM_SMEM (4 * (128 * 40 + 128 * 40) * 2)   // 81920 bytes

template <int MODE>
__global__ void __launch_bounds__(256, 2) mm_kernel(
    const __nv_bfloat16* __restrict__ A, long long sAi,
    const __nv_bfloat16* __restrict__ B, long long sBi,
    const float* __restrict__ bias,
    __nv_bfloat16* __restrict__ C, long long sCi,
    int Nreal, int Kdim)
{
    int Mreal = g_Ntot * LL;
    int m0 = blockIdx.y * 128;
    if (m0 >= Mreal) return;
    int n0 = blockIdx.x * 128;
    size_t stA = (size_t)sAi, stB = (size_t)sBi;
    int Ktiles = Kdim >> 5;

    extern __shared__ __nv_bfloat16 sm[];
    __nv_bfloat16* As = sm;                    // [4][128][40]
    __nv_bfloat16* Bs = sm + 4 * 128 * 40;     // [4][128][40]

    int tid = threadIdx.x;
    int lane = tid & 31;
    int w = tid >> 5;
    int wm = w >> 1;   // 0..3 (32 rows each)
    int wn = w & 1;    // 0..1 (64 cols each)

    float acc[2][8][4];
#pragma unroll
    for (int i = 0; i < 2; i++)
#pragma unroll
        for (int j = 0; j < 8; j++)
#pragma unroll
            for (int q = 0; q < 4; q++) acc[i][j][q] = 0.f;

    auto load_tile = [&](int kt, int s) {
        __nv_bfloat16* as = As + s * 128 * 40;
        __nv_bfloat16* bs = Bs + s * 128 * 40;
#pragma unroll
        for (int i = 0; i < 2; i++) {
            int c = tid + i * 256;
            int r = c >> 2, ko = (c & 3) * 8;
            int m = imin(m0 + r, Mreal - 1);
            cp16(smem_u32(&as[r * 40 + ko]), A + (size_t)m * stA + (size_t)kt * 32 + ko);
        }
#pragma unroll
        for (int i = 0; i < 2; i++) {
            int c = tid + i * 256;
            int r = c >> 2, ko = (c & 3) * 8;
            int n = imin(n0 + r, Nreal - 1);
            cp16(smem_u32(&bs[r * 40 + ko]), B + (size_t)n * stB + (size_t)kt * 32 + ko);
        }
    };

    load_tile(0, 0); cp_commit();
    if (Ktiles > 1) load_tile(1, 1);
    cp_commit();

    for (int kt = 0; kt < Ktiles; kt++) {
        if (kt + 2 < Ktiles) load_tile(kt + 2, (kt + 2) & 3);
        cp_commit();
        cp_wait2();
        __syncthreads();

        int s = kt & 3;
        const __nv_bfloat16* as = As + s * 128 * 40;
        const __nv_bfloat16* bs = Bs + s * 128 * 40;
#pragma unroll
        for (int ks = 0; ks < 2; ks++) {
            int k0 = ks * 16;
            uint32_t a[2][4], bb[8][2];
#pragma unroll
            for (int mf = 0; mf < 2; mf++) {
                int row = wm * 32 + mf * 16 + (lane & 7) + ((lane >> 3) & 1) * 8;
                int col = k0 + (lane >> 4) * 8;
                ldmx4(a[mf][0], a[mf][1], a[mf][2], a[mf][3], smem_u32(&as[row * 40 + col]));
            }
#pragma unroll
            for (int ng = 0; ng < 4; ng++) {
                int row = wn * 64 + ng * 16 + (lane & 7) + (lane >> 4) * 8;
                int col = k0 + ((lane >> 3) & 1) * 8;
                uint32_t r0, r1, r2, r3;
                ldmx4(r0, r1, r2, r3, smem_u32(&bs[row * 40 + col]));
                bb[ng * 2][0] = r0;     bb[ng * 2][1] = r1;
                bb[ng * 2 + 1][0] = r2; bb[ng * 2 + 1][1] = r3;
            }
#pragma unroll
            for (int mf = 0; mf < 2; mf++)
#pragma unroll
                for (int nf = 0; nf < 8; nf++)
                    mma16816(acc[mf][nf], a[mf], bb[nf]);
        }
    }

    int width = (int)sCi;
#pragma unroll
    for (int mf = 0; mf < 2; mf++) {
#pragma unroll
        for (int nf = 0; nf < 8; nf++) {
            int rbase = m0 + wm * 32 + mf * 16 + (lane >> 2);
            int cbase = n0 + wn * 64 + nf * 8 + (lane & 3) * 2;
            if (cbase >= width) continue;
#pragma unroll
            for (int q = 0; q < 2; q++) {
                int m = rbase + q * 8;
                if (m >= Mreal) continue;
                float v0 = (cbase < Nreal)     ? acc[mf][nf][q * 2]     + bias[cbase]     : 0.f;
                float v1 = (cbase + 1 < Nreal) ? acc[mf][nf][q * 2 + 1] + bias[cbase + 1] : 0.f;
                if (MODE == 1) { v0 = fmaxf(v0, 0.f); v1 = fmaxf(v1, 0.f); }
                if (MODE == 2) { v0 = tanhf(v0); v1 = tanhf(v1); }
                *(__nv_bfloat162*)(C + (size_t)m * width + cbase) = __floats2bfloat162_rn(v0, v1);
            }
        }
    }
}

// ---------------- fused attention ----------------
#define SP_STRIDE 520
#define SM_SP  0
#define SM_Q   (64 * SP_STRIDE * 2)
#define SM_KV  (SM_Q + 64 * 72 * 2)
#define SM_MSK (SM_KV + 2 * 64 * 72 * 2)
#define ATTN_SMEM (SM_MSK + 512 * 4)

__global__ void __launch_bounds__(256) attn_kernel(
    const __nv_bfloat16* __restrict__ QKV, __nv_bfloat16* __restrict__ ATT)
{
    int Nt = g_Ntot;
    int n0 = blockIdx.x * 64;
    if (n0 >= Nt) return;
    int z = blockIdx.y;
    int l = z / HH, h = z % HH;
    int Kc = (Nt + 63) & ~63;
    int Mtiles = Kc >> 6;

    extern __shared__ char smem[];
    __nv_bfloat16* SP = (__nv_bfloat16*)(smem + SM_SP);
    __nv_bfloat16* Qs = (__nv_bfloat16*)(smem + SM_Q);
    __nv_bfloat16* KV = (__nv_bfloat16*)(smem + SM_KV);
    float*        msk = (float*)(smem + SM_MSK);

    int tid = threadIdx.x;
    int lane = tid & 31;
    int w = tid >> 5;
    int wm = w >> 1;
    int wn = w & 1;

    for (int j = tid; j < 512; j += 256)
        msk[j] = (j < Nt) ? g_MSK[j * LL + l] : -1e30f;

#pragma unroll
    for (int i = 0; i < 2; i++) {
        int c = tid + i * 256;
        int r = c >> 3, co = (c & 7) * 8;
        int n = imin(n0 + r, Nt - 1);
        cp16(smem_u32(&Qs[r * 72 + co]), QKV + ((size_t)n * LL + l) * (3 * DM) + h * HD + co);
    }

    auto load_kv = [&](int mt, int buf, int which) {
#pragma unroll
        for (int i = 0; i < 2; i++) {
            int c = tid + i * 256;
            int r = c >> 3, co = (c & 7) * 8;
            int m = imin(mt * 64 + r, Nt - 1);
            cp16(smem_u32(&KV[(buf * 64 + r) * 72 + co]),
                 QKV + ((size_t)m * LL + l) * (3 * DM) + which * DM + h * HD + co);
        }
    };

    load_kv(0, 0, 1);
    cp_commit();

    for (int mt = 0; mt < Mtiles; mt++) {
        int buf = mt & 1;
        if (mt + 1 < Mtiles) { load_kv(mt + 1, buf ^ 1, 1); cp_commit(); cp_wait1(); }
        else cp_wait0();
        __syncthreads();

        float acc[4][4];
#pragma unroll
        for (int j = 0; j < 4; j++)
#pragma unroll
            for (int q = 0; q < 4; q++) acc[j][q] = 0.f;

#pragma unroll
        for (int ks = 0; ks < 4; ks++) {
            int k0 = ks * 16;
            uint32_t a[4], bb[4][2];
            {
                int row = wm * 16 + (lane & 7) + ((lane >> 3) & 1) * 8;
                int col = k0 + (lane >> 4) * 8;
                ldmx4(a[0], a[1], a[2], a[3], smem_u32(&Qs[row * 72 + col]));
            }
#pragma unroll
            for (int ng = 0; ng < 2; ng++) {
                int row = wn * 32 + ng * 16 + (lane & 7) + (lane >> 4) * 8;
                int col = k0 + ((lane >> 3) & 1) * 8;
                uint32_t r0, r1, r2, r3;
                ldmx4(r0, r1, r2, r3, smem_u32(&KV[(buf * 64 + row) * 72 + col]));
                bb[ng * 2][0] = r0;     bb[ng * 2][1] = r1;
                bb[ng * 2 + 1][0] = r2; bb[ng * 2 + 1][1] = r3;
            }
#pragma unroll
            for (int nf = 0; nf < 4; nf++) mma16816(acc[nf], a, bb[nf]);
        }
        int rbase = wm * 16 + (lane >> 2);
#pragma unroll
        for (int nf = 0; nf < 4; nf++) {
            int cl = wn * 32 + nf * 8 + (lane & 3) * 2;
            int gc = mt * 64 + cl;
            float m0v = msk[gc], m1v = msk[gc + 1];
#pragma unroll
            for (int q = 0; q < 2; q++) {
                int r = rbase + q * 8;
                float v0 = acc[nf][q * 2]     * 0.125f + m0v;
                float v1 = acc[nf][q * 2 + 1] * 0.125f + m1v;
                *(__nv_bfloat162*)&SP[r * SP_STRIDE + gc] = __floats2bfloat162_rn(v0, v1);
            }
        }
        __syncthreads();
    }

    {
        int cnt = Kc >> 5;
        for (int rr = 0; rr < 8; rr++) {
            int r = w * 8 + rr;
            float vals[16];
            float mx = -INFINITY;
            for (int i = 0; i < cnt; i++) {
                vals[i] = __bfloat162float(SP[r * SP_STRIDE + lane + i * 32]);
                mx = fmaxf(mx, vals[i]);
            }
#pragma unroll
            for (int o = 16; o > 0; o >>= 1) mx = fmaxf(mx, __shfl_xor_sync(0xffffffff, mx, o));
            float sum = 0.f;
            for (int i = 0; i < cnt; i++) { vals[i] = fexp(vals[i] - mx); sum += vals[i]; }
#pragma unroll
            for (int o = 16; o > 0; o >>= 1) sum += __shfl_xor_sync(0xffffffff, sum, o);
            float inv = 1.f / sum;
            for (int i = 0; i < cnt; i++)
                SP[r * SP_STRIDE + lane + i * 32] = __float2bfloat16(vals[i] * inv);
        }
    }
    __syncthreads();

    float oacc[4][4];
#pragma unroll
    for (int j = 0; j < 4; j++)
#pragma unroll
        for (int q = 0; q < 4; q++) oacc[j][q] = 0.f;

    load_kv(0, 0, 2);
    cp_commit();

    for (int mt = 0; mt < Mtiles; mt++) {
        int buf = mt & 1;
        if (mt + 1 < Mtiles) { load_kv(mt + 1, buf ^ 1, 2); cp_commit(); cp_wait1(); }
        else cp_wait0();
        __syncthreads();

#pragma unroll
        for (int ks = 0; ks < 4; ks++) {
            int mk0 = mt * 64 + ks * 16;
            uint32_t a[4], bb[4][2];
            {
                int row = wm * 16 + (lane & 7) + ((lane >> 3) & 1) * 8;
                int col = mk0 + (lane >> 4) * 8;
                ldmx4(a[0], a[1], a[2], a[3], smem_u32(&SP[row * SP_STRIDE + col]));
            }
#pragma unroll
            for (int ng = 0; ng < 2; ng++) {
                int vrow = ks * 16 + (lane & 7) + ((lane >> 3) & 1) * 8;
                int vcol = wn * 32 + ng * 16 + (lane >> 4) * 8;
                uint32_t r0, r1, r2, r3;
                ldmx4t(r0, r1, r2, r3, smem_u32(&KV[(buf * 64 + vrow) * 72 + vcol]));
                bb[ng * 2][0] = r0;     bb[ng * 2][1] = r1;
                bb[ng * 2 + 1][0] = r2; bb[ng * 2 + 1][1] = r3;
            }
#pragma unroll
            for (int nf = 0; nf < 4; nf++) mma16816(oacc[nf], a, bb[nf]);
        }
        __syncthreads();
    }

    int rbase = wm * 16 + (lane >> 2);
#pragma unroll
    for (int nf = 0; nf < 4; nf++) {
        int c = wn * 32 + nf * 8 + (lane & 3) * 2;
#pragma unroll
        for (int q = 0; q < 2; q++) {
            int n = n0 + rbase + q * 8;
            if (n < Nt) {
                __nv_bfloat16* row = ATT + ((size_t)n * LL + l) * DM + h * HD + c;
                *(__nv_bfloat162*)row =
                    __floats2bfloat162_rn(oacc[nf][q * 2], oacc[nf][q * 2 + 1]);
            }
        }
    }
}

// ---------------- residual + LayerNorm ----------------
__global__ void add_ln_kernel(__nv_bfloat16* __restrict__ X, const __nv_bfloat16* __restrict__ Yv,
                              const float* __restrict__ g, const float* __restrict__ b) {
    int row = blockIdx.x;
    if (row >= g_Ntot * LL) return;
    __nv_bfloat16* x = X + (size_t)row * DM;
    const __nv_bfloat16* y = Yv + (size_t)row * DM;
    int t = threadIdx.x;
    float v[3], s = 0.f, s2 = 0.f;
#pragma unroll
    for (int i = 0; i < 3; i++) {
        int d = t + 256 * i;
        float u = __bfloat162float(x[d]) + __bfloat162float(y[d]);
        v[i] = u; s += u; s2 += u * u;
    }
    __shared__ float rs[256], rs2[256];
    rs[t] = s; rs2[t] = s2; __syncthreads();
    for (int st = 128; st > 0; st >>= 1) {
        if (t < st) { rs[t] += rs[t + st]; rs2[t] += rs2[t + st]; }
        __syncthreads();
    }
    float mean = rs[0] * (1.f / (float)DM);
    float var = rs2[0] * (1.f / (float)DM) - mean * mean;
    float inv = rsqrtf(var + 1e-5f);
#pragma unroll
    for (int i = 0; i < 3; i++) {
        int d = t + 256 * i;
        x[d] = __float2bfloat16((v[i] - mean) * inv * g[d] + b[d]);
    }
}

// ---------------- anomaly ----------------
__global__ void anomaly_kernel() {
    int n = blockIdx.x;
    if (n >= g_Ntot) return;
    int t = threadIdx.x;
    float acc = 0.f;
#pragma unroll
    for (int i = 0; i < 3; i++) {
        int d = t + 256 * i;
        float m = 0.f;
        for (int l = 0; l < LL; l++)
            m += __bfloat162float(g_Xbf[((size_t)n * LL + l) * DM + d]);
        m *= (1.f / (float)LL);
        float diff = m - g_meanE[n * DM + d];
        acc += diff * diff;
    }
    __shared__ float red[256];
    red[t] = acc; __syncthreads();
    for (int s = 128; s > 0; s >>= 1) { if (t < s) red[t] += red[t + s]; __syncthreads(); }
    if (t == 0) g_s[n] = red[0];
}

// ---------------- selection ----------------
__global__ void select_kernel() {
    int b = threadIdx.x;
    if (b >= BB) return;
    int nr = g_nresp[b];
    int ne = g_next[b];
    bool used[TT];
    int ohf[TT];
#pragma unroll
    for (int j = 0; j < TT; j++) { used[j] = false; ohf[j] = 0; }
    ohf[0] = 1;
    g_nodefull[b * TT + 0] = 0;
    for (int i = 0; i < TT - 1; i++) {
        int node = 0;
        if (i < ne) {
            float best = INFINITY; int bj = 0;
            for (int j = 0; j < nr; j++) {
                if (!used[j] && g_s[j] < best) { best = g_s[j]; bj = j; }
            }
            used[bj] = true;
            node = bj + 1;
            ohf[node] = 1;
        }
        g_nodefull[b * TT + i + 1] = node;
    }
    for (int t = 0; t < TT; t++) g_oh[b * TT + t] = ohf[t];
}

// ---------------- output writers ----------------
__global__ void out_small_kernel(float* __restrict__ out, long long off_oh,
                                 long long off_sc, long long off_tl, int has_sc) {
    int t = blockIdx.x * blockDim.x + threadIdx.x;
    if (t < BB * TT) out[off_oh + t] = (float)g_oh[t];
    else if (t < BB * TT + BB) out[off_tl + (t - BB * TT)] = (float)(1 + g_next[t - BB * TT]);
    else if (t == BB * TT + BB && has_sc) out[off_sc] = 0.f;
}
__global__ void ext_mask_kernel(float* __restrict__ out, long long off) {
    int bt = blockIdx.x;
    out[off + (size_t)bt * LL + threadIdx.x] = (float)g_oh[bt];
}
__global__ void new_msk_kernel(const float* __restrict__ amask,
                               float* __restrict__ out, long long off) {
    int bt = blockIdx.x;
    int b = bt >> 5, t = bt & 31;
    int node = g_nodefull[bt];
    float valid = (t == 0 || (t - 1) < g_next[b]) ? 1.f : 0.f;
    out[off + (size_t)bt * LL + threadIdx.x] =
        amask[((size_t)b * TT + node) * LL + threadIdx.x] * valid;
}
__global__ void new_emb_kernel(const float* __restrict__ emb,
                               float* __restrict__ out, long long off) {
    int bt = blockIdx.x / 192;
    int r = (blockIdx.x % 192) * 256 + threadIdx.x;
    int b = bt >> 5;
    int node = g_nodefull[bt];
    out[off + (size_t)bt * (LL * DM) + r] =
        emb[((size_t)b * TT + node) * (LL * DM) + r];
}

// ---------------- host ----------------
static void run_layer(__nv_bfloat16* pW, int qkvOff, int outOff, int w1Off, int w2Off,
                      const float* qkvb, const float* outb,
                      const float* g1, const float* b1,
                      const float* c1, const float* c2,
                      const float* g2, const float* b2,
                      __nv_bfloat16* pX, __nv_bfloat16* pQKV, __nv_bfloat16* pATT,
                      __nv_bfloat16* pY, __nv_bfloat16* pHID) {
    const int GY = 248;  // ceil(NMAX*64 / 128)
    mm_kernel<0><<<dim3(18, GY), 256, MM_SMEM>>>(pX, DM, pW + qkvOff, DM, qkvb, pQKV, 3 * DM, 3 * DM, DM);
    attn_kernel<<<dim3(8, 768), 256, ATTN_SMEM>>>(pQKV, pATT);
    mm_kernel<0><<<dim3(6, GY), 256, MM_SMEM>>>(pATT, DM, pW + outOff, DM, outb, pY, DM, DM, DM);
    add_ln_kernel<<<NMAX * LL, 256>>>(pX, pY, g1, b1);
    mm_kernel<1><<<dim3(16, GY), 256, MM_SMEM>>>(pX, DM, pW + w1Off, DM, c1, pHID, FF, FF, DM);
    mm_kernel<0><<<dim3(6, GY), 256, MM_SMEM>>>(pHID, FF, pW + w2Off, FF, c2, pY, DM, DM, FF);
    add_ln_kernel<<<NMAX * LL, 256>>>(pX, pY, g2, b2);
}

extern "C" void kernel_launch(void* const* d_in, const int* in_sizes, int n_in,
                              void* d_out, int out_size) {
    const int*   tree_lens = (const int*)d_in[0];
    const float* emb       = (const float*)d_in[1];
    const float* amask     = (const float*)d_in[2];
    const float* P[28];
    for (int i = 3; i < 31; i++) P[i - 3] = (const float*)d_in[i];
    float* out = (float*)d_out;

    __nv_bfloat16 *pX, *pQKV, *pATT, *pY, *pHID, *pZ, *pW;
    cudaGetSymbolAddress((void**)&pX, g_Xbf);
    cudaGetSymbolAddress((void**)&pQKV, g_QKVbf);
    cudaGetSymbolAddress((void**)&pATT, g_ATTbf);
    cudaGetSymbolAddress((void**)&pY, g_Ybf);
    cudaGetSymbolAddress((void**)&pHID, g_HIDbf);
    cudaGetSymbolAddress((void**)&pZ, g_Zbf);
    cudaGetSymbolAddress((void**)&pW, g_Wbf);

    cudaFuncSetAttribute(attn_kernel, cudaFuncAttributeMaxDynamicSharedMemorySize, ATTN_SMEM);
    cudaFuncSetAttribute(mm_kernel<0>, cudaFuncAttributeMaxDynamicSharedMemorySize, MM_SMEM);
    cudaFuncSetAttribute(mm_kernel<1>, cudaFuncAttributeMaxDynamicSharedMemorySize, MM_SMEM);
    cudaFuncSetAttribute(mm_kernel<2>, cudaFuncAttributeMaxDynamicSharedMemorySize, MM_SMEM);

    const long long NE_ELEMS = (long long)BB * TT * LL * DM;
    const long long TOT_W = 512 + 32768 + 1 + 16 + NE_ELEMS + 32768;
    int has_sc = ((long long)out_size == TOT_W - 1) ? 0 : 1;
    long long off_oh = 0;
    long long off_em = 512;
    long long off_sc = 512 + 32768;
    long long off_tl = off_sc + (has_sc ? 1 : 0);
    long long off_ne = off_tl + 16;
    long long off_nm = off_ne + NE_ELEMS;

    setup_kernel<<<1, 32>>>(tree_lens);
    gather_kernel<<<dim3(NMAX, LL), 256>>>(emb, amask);
    meanE_kernel<<<dim3(NMAX, 3), 256>>>(emb);

    conv_kernel<<<1024, 256>>>((const float4*)P[0],  (__nv_bfloat162*)(pW + OFF_EQKV), SZ_QKV / 4);
    conv_kernel<<<1024, 256>>>((const float4*)P[2],  (__nv_bfloat162*)(pW + OFF_EOUT), SZ_OUT / 4);
    conv_kernel<<<1024, 256>>>((const float4*)P[6],  (__nv_bfloat162*)(pW + OFF_EW1),  SZ_W1 / 4);
    conv_kernel<<<1024, 256>>>((const float4*)P[8],  (__nv_bfloat162*)(pW + OFF_EW2),  SZ_W2 / 4);
    conv_kernel<<<1024, 256>>>((const float4*)P[12], (__nv_bfloat162*)(pW + OFF_DQKV), SZ_QKV / 4);
    conv_kernel<<<1024, 256>>>((const float4*)P[14], (__nv_bfloat162*)(pW + OFF_DOUT), SZ_OUT / 4);
    conv_kernel<<<1024, 256>>>((const float4*)P[18], (__nv_bfloat162*)(pW + OFF_DW1),  SZ_W1 / 4);
    conv_kernel<<<1024, 256>>>((const float4*)P[20], (__nv_bfloat162*)(pW + OFF_DW2),  SZ_W2 / 4);
    conv_kernel<<<128, 256>>>((const float4*)P[24],  (__nv_bfloat162*)(pW + OFF_PE),   SZ_PE / 4);
    conv_pad_kernel<<<(DM * 128 + 255) / 256, 256>>>(P[26], pW + OFF_PD);

    const int LQKV = 3 * DM * DM, LOUT = DM * DM, LW1 = FF * DM, LW2 = DM * FF;
    for (int i = 0; i < 2; i++)
        run_layer(pW, OFF_EQKV + i * LQKV, OFF_EOUT + i * LOUT,
                  OFF_EW1 + i * LW1, OFF_EW2 + i * LW2,
                  P[1] + (size_t)i * 3 * DM, P[3] + (size_t)i * DM,
                  P[4] + (size_t)i * DM, P[5] + (size_t)i * DM,
                  P[7] + (size_t)i * FF, P[9] + (size_t)i * DM,
                  P[10] + (size_t)i * DM, P[11] + (size_t)i * DM,
                  pX, pQKV, pATT, pY, pHID);

    mm_kernel<2><<<dim3(1, 248), 256, MM_SMEM>>>(pX, DM, pW + OFF_PE, DM, P[25], pZ, 128, ZZ, DM);
    mm_kernel<2><<<dim3(6, 248), 256, MM_SMEM>>>(pZ, 128, pW + OFF_PD, 128, P[27], pX, DM, DM, 128);

    for (int i = 0; i < 2; i++)
        run_layer(pW, OFF_DQKV + i * LQKV, OFF_DOUT + i * LOUT,
                  OFF_DW1 + i * LW1, OFF_DW2 + i * LW2,
                  P[13] + (size_t)i * 3 * DM, P[15] + (size_t)i * DM,
                  P[16] + (size_t)i * DM, P[17] + (size_t)i * DM,
                  P[19] + (size_t)i * FF, P[21] + (size_t)i * DM,
                  P[22] + (size_t)i * DM, P[23] + (size_t)i * DM,
                  pX, pQKV, pATT, pY, pHID);

    anomaly_kernel<<<NMAX, 256>>>();
    select_kernel<<<1, 32>>>();

    out_small_kernel<<<3, 256>>>(out, off_oh, off_sc, off_tl, has_sc);
    ext_mask_kernel<<<BB * TT, LL>>>(out, off_em);
    new_msk_kernel<<<BB * TT, LL>>>(amask, out, off_nm);
    new_emb_kernel<<<BB * TT * 192, 256>>>(emb, out, off_ne);
}

// round 10
// speedup vs baseline: 1.2453x; 1.0886x over previous
#include <cuda_runtime.h>
#include <cuda_bf16.h>
#include <math.h>
#include <stdint.h>

#define BB   16
#define TT   32
#define LL   64
#define DM   768
#define HH   12
#define HD   64
#define FF   2048
#define ZZ   100
#define NMAX 496
#define MROWS (NMAX * LL)

// ---------------- helpers ----------------
__device__ __forceinline__ uint32_t smem_u32(const void* p) {
    uint32_t a;
    asm("{ .reg .u64 t; cvta.to.shared.u64 t, %1; cvt.u32.u64 %0, t; }" : "=r"(a) : "l"(p));
    return a;
}
__device__ __forceinline__ void cp16(uint32_t dst, const void* src) {
    asm volatile("cp.async.cg.shared.global [%0], [%1], 16;" :: "r"(dst), "l"(src));
}
__device__ __forceinline__ void cp_commit() { asm volatile("cp.async.commit_group;" ::: "memory"); }
__device__ __forceinline__ void cp_wait0()  { asm volatile("cp.async.wait_group 0;" ::: "memory"); }
__device__ __forceinline__ void cp_wait1()  { asm volatile("cp.async.wait_group 1;" ::: "memory"); }
__device__ __forceinline__ void cp_wait2()  { asm volatile("cp.async.wait_group 2;" ::: "memory"); }
__device__ __forceinline__ void ldmx4(uint32_t& r0, uint32_t& r1, uint32_t& r2, uint32_t& r3,
                                      uint32_t addr) {
    asm volatile("ldmatrix.sync.aligned.m8n8.x4.shared.b16 {%0,%1,%2,%3}, [%4];"
                 : "=r"(r0), "=r"(r1), "=r"(r2), "=r"(r3) : "r"(addr));
}
__device__ __forceinline__ void ldmx4t(uint32_t& r0, uint32_t& r1, uint32_t& r2, uint32_t& r3,
                                       uint32_t addr) {
    asm volatile("ldmatrix.sync.aligned.m8n8.x4.trans.shared.b16 {%0,%1,%2,%3}, [%4];"
                 : "=r"(r0), "=r"(r1), "=r"(r2), "=r"(r3) : "r"(addr));
}
__device__ __forceinline__ void mma16816(float* c, const uint32_t* a, const uint32_t* b) {
    asm volatile("mma.sync.aligned.m16n8k16.row.col.f32.bf16.bf16.f32 "
                 "{%0,%1,%2,%3}, {%4,%5,%6,%7}, {%8,%9}, {%0,%1,%2,%3};"
                 : "+f"(c[0]), "+f"(c[1]), "+f"(c[2]), "+f"(c[3])
                 : "r"(a[0]), "r"(a[1]), "r"(a[2]), "r"(a[3]), "r"(b[0]), "r"(b[1]));
}
__device__ __forceinline__ int imin(int a, int b) { return a < b ? a : b; }
__device__ __forceinline__ uint32_t packbf(float x, float y) {
    uint32_t r;
    asm("cvt.rn.bf16x2.f32 %0, %1, %2;" : "=r"(r) : "f"(y), "f"(x));
    return r;
}

// fast exp on the FMA pipe; x <= 0 expected
__device__ __forceinline__ float fexp(float x) {
    float t = x * 1.44269504f;
    t = fmaxf(t, -125.0f);
    float e = floorf(t);
    float f = t - e;
    float p = 1.0f + f * (0.69314718f + f * (0.24022651f + f * (0.05550411f +
              f * (0.00961813f + f * 0.00133336f))));
    return p * __int_as_float(((int)e + 127) << 23);
}

// ---------------- device scratch ----------------
__device__ __nv_bfloat16 g_Xbf  [MROWS * DM];
__device__ __nv_bfloat16 g_QKVbf[MROWS * 3 * DM];
__device__ __nv_bfloat16 g_ATTbf[MROWS * DM];
__device__ __nv_bfloat16 g_Ybf  [MROWS * DM];
__device__ __nv_bfloat16 g_HIDbf[MROWS * FF];
__device__ __nv_bfloat16 g_Zbf  [MROWS * 128];

#define OFF_EQKV 0
#define SZ_QKV   (2 * 3 * DM * DM)
#define OFF_EOUT (OFF_EQKV + SZ_QKV)
#define SZ_OUT   (2 * DM * DM)
#define OFF_EW1  (OFF_EOUT + SZ_OUT)
#define SZ_W1    (2 * FF * DM)
#define OFF_EW2  (OFF_EW1 + SZ_W1)
#define SZ_W2    (2 * DM * FF)
#define OFF_DQKV (OFF_EW2 + SZ_W2)
#define OFF_DOUT (OFF_DQKV + SZ_QKV)
#define OFF_DW1  (OFF_DOUT + SZ_OUT)
#define OFF_DW2  (OFF_DW1 + SZ_W1)
#define OFF_PE   (OFF_DW2 + SZ_W2)
#define SZ_PE    (ZZ * DM)
#define OFF_PD   (OFF_PE + SZ_PE)
#define SZ_PD    (DM * 128)
#define WPOOL_SZ (OFF_PD + SZ_PD)
__device__ __nv_bfloat16 g_Wbf[WPOOL_SZ];

__device__ float g_MSK[NMAX * LL];
__device__ float g_meanE[NMAX * DM];
__device__ float g_s[NMAX];
__device__ int   g_Ntot;
__device__ int   g_nresp[BB];
__device__ int   g_next[BB];
__device__ int   g_bidx[NMAX];
__device__ int   g_tidx[NMAX];
__device__ int   g_nodefull[BB * TT];
__device__ int   g_oh[BB * TT];

// ---------------- setup / gather ----------------
__global__ void setup_kernel(const int* __restrict__ tree_lens) {
    if (threadIdx.x == 0 && blockIdx.x == 0) {
        int tot = 0;
        for (int b = 0; b < BB; b++) {
            int tl = tree_lens[b];
            int nr = tl - 1;
            g_nresp[b] = nr;
            int ne = (int)floor((double)nr * 0.05);
            if (ne < 1) ne = 1;
            g_next[b] = ne;
            for (int j = 1; j < tl; j++) { g_bidx[tot] = b; g_tidx[tot] = j; tot++; }
        }
        g_Ntot = tot;
    }
}

__global__ void gather_kernel(const float* __restrict__ emb, const float* __restrict__ amask) {
    int n = blockIdx.x, l = blockIdx.y;
    if (n >= g_Ntot) return;
    int bi = g_bidx[n], ti = g_tidx[n];
    const float* src = emb + (((size_t)bi * TT + ti) * LL + l) * DM;
    __nv_bfloat16* dst = g_Xbf + ((size_t)n * LL + l) * DM;
    for (int d = threadIdx.x; d < DM; d += blockDim.x) dst[d] = __float2bfloat16(src[d]);
    if (threadIdx.x == 0)
        g_MSK[n * LL + l] = amask[((size_t)bi * TT + ti) * LL + l];
}

__global__ void meanE_kernel(const float* __restrict__ emb) {
    int n = blockIdx.x;
    if (n >= g_Ntot) return;
    int d = blockIdx.y * 256 + threadIdx.x;
    int bi = g_bidx[n], ti = g_tidx[n];
    const float* base = emb + ((size_t)bi * TT + ti) * LL * DM;
    float s = 0.f;
    for (int l = 0; l < LL; l++) s += base[(size_t)l * DM + d];
    g_meanE[n * DM + d] = s * (1.f / (float)LL);
}

// ---------------- weight converts (vectorized) ----------------
__global__ void conv_kernel(const float4* __restrict__ src, __nv_bfloat162* __restrict__ dst,
                            int cnt4) {
    for (int i = blockIdx.x * blockDim.x + threadIdx.x; i < cnt4; i += gridDim.x * blockDim.x) {
        float4 v = src[i];
        dst[2 * i]     = __floats2bfloat162_rn(v.x, v.y);
        dst[2 * i + 1] = __floats2bfloat162_rn(v.z, v.w);
    }
}
__global__ void conv_pad_kernel(const float* __restrict__ src, __nv_bfloat16* __restrict__ dst) {
    int i = blockIdx.x * blockDim.x + threadIdx.x;
    if (i >= DM * 128) return;
    int r = i >> 7, c = i & 127;
    dst[i] = __float2bfloat16((c < ZZ) ? src[r * ZZ + c] : 0.f);
}

// ---------------- warp-MMA GEMM: 128x128x32 block, 8 warps, warp tile 32x64 ----------------
#define MM_SMEM (4 * (128 * 40 + 128 * 40) * 2)   // 81920 bytes

template <int MODE>
__global__ void __launch_bounds__(256, 2) mm_kernel(
    const __nv_bfloat16* __restrict__ A, long long sAi,
    const __nv_bfloat16* __restrict__ B, long long sBi,
    const float* __restrict__ bias,
    __nv_bfloat16* __restrict__ C, long long sCi,
    int Nreal, int Kdim)
{
    int Mreal = g_Ntot * LL;
    int m0 = blockIdx.y * 128;
    if (m0 >= Mreal) return;
    int n0 = blockIdx.x * 128;
    size_t stA = (size_t)sAi, stB = (size_t)sBi;
    int Ktiles = Kdim >> 5;

    extern __shared__ __nv_bfloat16 sm[];
    __nv_bfloat16* As = sm;
    __nv_bfloat16* Bs = sm + 4 * 128 * 40;

    int tid = threadIdx.x;
    int lane = tid & 31;
    int w = tid >> 5;
    int wm = w >> 1;
    int wn = w & 1;

    float acc[2][8][4];
#pragma unroll
    for (int i = 0; i < 2; i++)
#pragma unroll
        for (int j = 0; j < 8; j++)
#pragma unroll
            for (int q = 0; q < 4; q++) acc[i][j][q] = 0.f;

    auto load_tile = [&](int kt, int s) {
        __nv_bfloat16* as = As + s * 128 * 40;
        __nv_bfloat16* bs = Bs + s * 128 * 40;
#pragma unroll
        for (int i = 0; i < 2; i++) {
            int c = tid + i * 256;
            int r = c >> 2, ko = (c & 3) * 8;
            int m = imin(m0 + r, Mreal - 1);
            cp16(smem_u32(&as[r * 40 + ko]), A + (size_t)m * stA + (size_t)kt * 32 + ko);
        }
#pragma unroll
        for (int i = 0; i < 2; i++) {
            int c = tid + i * 256;
            int r = c >> 2, ko = (c & 3) * 8;
            int n = imin(n0 + r, Nreal - 1);
            cp16(smem_u32(&bs[r * 40 + ko]), B + (size_t)n * stB + (size_t)kt * 32 + ko);
        }
    };

    load_tile(0, 0); cp_commit();
    if (Ktiles > 1) load_tile(1, 1);
    cp_commit();

    for (int kt = 0; kt < Ktiles; kt++) {
        if (kt + 2 < Ktiles) load_tile(kt + 2, (kt + 2) & 3);
        cp_commit();
        cp_wait2();
        __syncthreads();

        int s = kt & 3;
        const __nv_bfloat16* as = As + s * 128 * 40;
        const __nv_bfloat16* bs = Bs + s * 128 * 40;
#pragma unroll
        for (int ks = 0; ks < 2; ks++) {
            int k0 = ks * 16;
            uint32_t a[2][4], bb[8][2];
#pragma unroll
            for (int mf = 0; mf < 2; mf++) {
                int row = wm * 32 + mf * 16 + (lane & 7) + ((lane >> 3) & 1) * 8;
                int col = k0 + (lane >> 4) * 8;
                ldmx4(a[mf][0], a[mf][1], a[mf][2], a[mf][3], smem_u32(&as[row * 40 + col]));
            }
#pragma unroll
            for (int ng = 0; ng < 4; ng++) {
                int row = wn * 64 + ng * 16 + (lane & 7) + (lane >> 4) * 8;
                int col = k0 + ((lane >> 3) & 1) * 8;
                uint32_t r0, r1, r2, r3;
                ldmx4(r0, r1, r2, r3, smem_u32(&bs[row * 40 + col]));
                bb[ng * 2][0] = r0;     bb[ng * 2][1] = r1;
                bb[ng * 2 + 1][0] = r2; bb[ng * 2 + 1][1] = r3;
            }
#pragma unroll
            for (int mf = 0; mf < 2; mf++)
#pragma unroll
                for (int nf = 0; nf < 8; nf++)
                    mma16816(acc[mf][nf], a[mf], bb[nf]);
        }
    }

    int width = (int)sCi;
#pragma unroll
    for (int mf = 0; mf < 2; mf++) {
#pragma unroll
        for (int nf = 0; nf < 8; nf++) {
            int rbase = m0 + wm * 32 + mf * 16 + (lane >> 2);
            int cbase = n0 + wn * 64 + nf * 8 + (lane & 3) * 2;
            if (cbase >= width) continue;
#pragma unroll
            for (int q = 0; q < 2; q++) {
                int m = rbase + q * 8;
                if (m >= Mreal) continue;
                float v0 = (cbase < Nreal)     ? acc[mf][nf][q * 2]     + bias[cbase]     : 0.f;
                float v1 = (cbase + 1 < Nreal) ? acc[mf][nf][q * 2 + 1] + bias[cbase + 1] : 0.f;
                if (MODE == 1) { v0 = fmaxf(v0, 0.f); v1 = fmaxf(v1, 0.f); }
                if (MODE == 2) { v0 = tanhf(v0); v1 = tanhf(v1); }
                *(__nv_bfloat162*)(C + (size_t)m * width + cbase) = __floats2bfloat162_rn(v0, v1);
            }
        }
    }
}

// ---------------- flash attention: single pass, online softmax in registers ----------------
#define FA_Q   0
#define FA_K   (128 * 72 * 2)
#define FA_V   (FA_K + 2 * 64 * 72 * 2)
#define FA_MSK (FA_V + 2 * 64 * 72 * 2)
#define FA_SMEM (FA_MSK + 512 * 4)

__global__ void __launch_bounds__(256) attn_kernel(
    const __nv_bfloat16* __restrict__ QKV, __nv_bfloat16* __restrict__ ATT)
{
    int Nt = g_Ntot;
    int n0 = blockIdx.x * 128;
    if (n0 >= Nt) return;
    int z = blockIdx.y;
    int l = z / HH, h = z % HH;
    int Mtiles = (Nt + 63) >> 6;

    extern __shared__ char smem[];
    __nv_bfloat16* Qs = (__nv_bfloat16*)(smem + FA_Q);
    __nv_bfloat16* Ks = (__nv_bfloat16*)(smem + FA_K);
    __nv_bfloat16* Vs = (__nv_bfloat16*)(smem + FA_V);
    float*        msk = (float*)(smem + FA_MSK);

    int tid = threadIdx.x;
    int lane = tid & 31;
    int w = tid >> 5;

    for (int j = tid; j < 512; j += 256)
        msk[j] = (j < Nt) ? g_MSK[j * LL + l] : -1e30f;

#pragma unroll
    for (int i = 0; i < 4; i++) {
        int c = tid + i * 256;
        int r = c >> 3, co = (c & 7) * 8;
        int n = imin(n0 + r, Nt - 1);
        cp16(smem_u32(&Qs[r * 72 + co]), QKV + ((size_t)n * LL + l) * (3 * DM) + h * HD + co);
    }
    cp_commit();

    auto load_kv = [&](int mt, int buf) {
#pragma unroll
        for (int i = 0; i < 2; i++) {
            int c = tid + i * 256;
            int r = c >> 3, co = (c & 7) * 8;
            int m = imin(mt * 64 + r, Nt - 1);
            const __nv_bfloat16* base = QKV + ((size_t)m * LL + l) * (3 * DM) + h * HD + co;
            cp16(smem_u32(&Ks[(buf * 64 + r) * 72 + co]), base + DM);
            cp16(smem_u32(&Vs[(buf * 64 + r) * 72 + co]), base + 2 * DM);
        }
    };

    load_kv(0, 0);
    cp_commit();
    cp_wait1();
    __syncthreads();

    uint32_t aq[4][4];
#pragma unroll
    for (int ks = 0; ks < 4; ks++) {
        int row = w * 16 + (lane & 7) + ((lane >> 3) & 1) * 8;
        int col = ks * 16 + (lane >> 4) * 8;
        ldmx4(aq[ks][0], aq[ks][1], aq[ks][2], aq[ks][3], smem_u32(&Qs[row * 72 + col]));
    }

    float oacc[8][4];
#pragma unroll
    for (int j = 0; j < 8; j++)
#pragma unroll
        for (int q = 0; q < 4; q++) oacc[j][q] = 0.f;
    float mrow[2] = { -1e30f, -1e30f };
    float lrow[2] = { 0.f, 0.f };

    for (int mt = 0; mt < Mtiles; mt++) {
        int buf = mt & 1;
        if (mt + 1 < Mtiles) { load_kv(mt + 1, buf ^ 1); cp_commit(); cp_wait1(); }
        else cp_wait0();
        __syncthreads();

        float sacc[8][4];
#pragma unroll
        for (int j = 0; j < 8; j++)
#pragma unroll
            for (int q = 0; q < 4; q++) sacc[j][q] = 0.f;

#pragma unroll
        for (int ks = 0; ks < 4; ks++) {
            uint32_t bb[8][2];
#pragma unroll
            for (int ng = 0; ng < 4; ng++) {
                int row = ng * 16 + (lane & 7) + (lane >> 4) * 8;
                int col = ks * 16 + ((lane >> 3) & 1) * 8;
                uint32_t r0, r1, r2, r3;
                ldmx4(r0, r1, r2, r3, smem_u32(&Ks[(buf * 64 + row) * 72 + col]));
                bb[ng * 2][0] = r0;     bb[ng * 2][1] = r1;
                bb[ng * 2 + 1][0] = r2; bb[ng * 2 + 1][1] = r3;
            }
#pragma unroll
            for (int nf = 0; nf < 8; nf++) mma16816(sacc[nf], aq[ks], bb[nf]);
        }

#pragma unroll
        for (int nf = 0; nf < 8; nf++) {
            int kc = mt * 64 + nf * 8 + (lane & 3) * 2;
            float mk0 = msk[kc], mk1 = msk[kc + 1];
            sacc[nf][0] = sacc[nf][0] * 0.125f + mk0;
            sacc[nf][1] = sacc[nf][1] * 0.125f + mk1;
            sacc[nf][2] = sacc[nf][2] * 0.125f + mk0;
            sacc[nf][3] = sacc[nf][3] * 0.125f + mk1;
        }

#pragma unroll
        for (int q = 0; q < 2; q++) {
            float tm = -1e30f;
#pragma unroll
            for (int nf = 0; nf < 8; nf++)
                tm = fmaxf(tm, fmaxf(sacc[nf][q * 2], sacc[nf][q * 2 + 1]));
            tm = fmaxf(tm, __shfl_xor_sync(0xffffffff, tm, 1));
            tm = fmaxf(tm, __shfl_xor_sync(0xffffffff, tm, 2));
            float mnew = fmaxf(mrow[q], tm);
            float sc = fexp(mrow[q] - mnew);
            float tsum = 0.f;
#pragma unroll
            for (int nf = 0; nf < 8; nf++) {
                float p0 = fexp(sacc[nf][q * 2]     - mnew);
                float p1 = fexp(sacc[nf][q * 2 + 1] - mnew);
                sacc[nf][q * 2] = p0; sacc[nf][q * 2 + 1] = p1;
                tsum += p0 + p1;
            }
            tsum += __shfl_xor_sync(0xffffffff, tsum, 1);
            tsum += __shfl_xor_sync(0xffffffff, tsum, 2);
            lrow[q] = lrow[q] * sc + tsum;
            mrow[q] = mnew;
#pragma unroll
            for (int nf = 0; nf < 8; nf++) {
                oacc[nf][q * 2]     *= sc;
                oacc[nf][q * 2 + 1] *= sc;
            }
        }

#pragma unroll
        for (int ks = 0; ks < 4; ks++) {
            uint32_t ap[4];
            ap[0] = packbf(sacc[2 * ks][0],     sacc[2 * ks][1]);
            ap[1] = packbf(sacc[2 * ks][2],     sacc[2 * ks][3]);
            ap[2] = packbf(sacc[2 * ks + 1][0], sacc[2 * ks + 1][1]);
            ap[3] = packbf(sacc[2 * ks + 1][2], sacc[2 * ks + 1][3]);
            uint32_t vb[8][2];
#pragma unroll
            for (int ng = 0; ng < 4; ng++) {
                int vrow = ks * 16 + (lane & 7) + ((lane >> 3) & 1) * 8;
                int vcol = ng * 16 + (lane >> 4) * 8;
                uint32_t r0, r1, r2, r3;
                ldmx4t(r0, r1, r2, r3, smem_u32(&Vs[(buf * 64 + vrow) * 72 + vcol]));
                vb[ng * 2][0] = r0;     vb[ng * 2][1] = r1;
                vb[ng * 2 + 1][0] = r2; vb[ng * 2 + 1][1] = r3;
            }
#pragma unroll
            for (int nf = 0; nf < 8; nf++) mma16816(oacc[nf], ap, vb[nf]);
        }
        __syncthreads();
    }

    float inv0 = 1.f / lrow[0];
    float inv1 = 1.f / lrow[1];
#pragma unroll
    for (int nf = 0; nf < 8; nf++) {
        int c = nf * 8 + (lane & 3) * 2;
#pragma unroll
        for (int q = 0; q < 2; q++) {
            int n = n0 + w * 16 + (lane >> 2) + q * 8;
            if (n < Nt) {
                float inv = q ? inv1 : inv0;
                __nv_bfloat16* row = ATT + ((size_t)n * LL + l) * DM + h * HD + c;
                *(__nv_bfloat162*)row =
                    __floats2bfloat162_rn(oacc[nf][q * 2] * inv, oacc[nf][q * 2 + 1] * inv);
            }
        }
    }
}

// ---------------- residual + LayerNorm ----------------
__global__ void add_ln_kernel(__nv_bfloat16* __restrict__ X, const __nv_bfloat16* __restrict__ Yv,
                              const float* __restrict__ g, const float* __restrict__ b) {
    int row = blockIdx.x;
    if (row >= g_Ntot * LL) return;
    __nv_bfloat16* x = X + (size_t)row * DM;
    const __nv_bfloat16* y = Yv + (size_t)row * DM;
    int t = threadIdx.x;
    float v[3], s = 0.f, s2 = 0.f;
#pragma unroll
    for (int i = 0; i < 3; i++) {
        int d = t + 256 * i;
        float u = __bfloat162float(x[d]) + __bfloat162float(y[d]);
        v[i] = u; s += u; s2 += u * u;
    }
    __shared__ float rs[256], rs2[256];
    rs[t] = s; rs2[t] = s2; __syncthreads();
    for (int st = 128; st > 0; st >>= 1) {
        if (t < st) { rs[t] += rs[t + st]; rs2[t] += rs2[t + st]; }
        __syncthreads();
    }
    float mean = rs[0] * (1.f / (float)DM);
    float var = rs2[0] * (1.f / (float)DM) - mean * mean;
    float inv = rsqrtf(var + 1e-5f);
#pragma unroll
    for (int i = 0; i < 3; i++) {
        int d = t + 256 * i;
        x[d] = __float2bfloat16((v[i] - mean) * inv * g[d] + b[d]);
    }
}

// ---------------- anomaly ----------------
__global__ void anomaly_kernel() {
    int n = blockIdx.x;
    if (n >= g_Ntot) return;
    int t = threadIdx.x;
    float acc = 0.f;
#pragma unroll
    for (int i = 0; i < 3; i++) {
        int d = t + 256 * i;
        float m = 0.f;
        for (int l = 0; l < LL; l++)
            m += __bfloat162float(g_Xbf[((size_t)n * LL + l) * DM + d]);
        m *= (1.f / (float)LL);
        float diff = m - g_meanE[n * DM + d];
        acc += diff * diff;
    }
    __shared__ float red[256];
    red[t] = acc; __syncthreads();
    for (int s = 128; s > 0; s >>= 1) { if (t < s) red[t] += red[t + s]; __syncthreads(); }
    if (t == 0) g_s[n] = red[0];
}

// ---------------- selection ----------------
__global__ void select_kernel() {
    int b = threadIdx.x;
    if (b >= BB) return;
    int nr = g_nresp[b];
    int ne = g_next[b];
    bool used[TT];
    int ohf[TT];
#pragma unroll
    for (int j = 0; j < TT; j++) { used[j] = false; ohf[j] = 0; }
    ohf[0] = 1;
    g_nodefull[b * TT + 0] = 0;
    for (int i = 0; i < TT - 1; i++) {
        int node = 0;
        if (i < ne) {
            float best = INFINITY; int bj = 0;
            for (int j = 0; j < nr; j++) {
                if (!used[j] && g_s[j] < best) { best = g_s[j]; bj = j; }
            }
            used[bj] = true;
            node = bj + 1;
            ohf[node] = 1;
        }
        g_nodefull[b * TT + i + 1] = node;
    }
    for (int t = 0; t < TT; t++) g_oh[b * TT + t] = ohf[t];
}

// ---------------- output writers ----------------
__global__ void out_small_kernel(float* __restrict__ out, long long off_oh,
                                 long long off_sc, long long off_tl, int has_sc) {
    int t = blockIdx.x * blockDim.x + threadIdx.x;
    if (t < BB * TT) out[off_oh + t] = (float)g_oh[t];
    else if (t < BB * TT + BB) out[off_tl + (t - BB * TT)] = (float)(1 + g_next[t - BB * TT]);
    else if (t == BB * TT + BB && has_sc) out[off_sc] = 0.f;
}
__global__ void ext_mask_kernel(float* __restrict__ out, long long off) {
    int bt = blockIdx.x;
    out[off + (size_t)bt * LL + threadIdx.x] = (float)g_oh[bt];
}
__global__ void new_msk_kernel(const float* __restrict__ amask,
                               float* __restrict__ out, long long off) {
    int bt = blockIdx.x;
    int b = bt >> 5, t = bt & 31;
    int node = g_nodefull[bt];
    float valid = (t == 0 || (t - 1) < g_next[b]) ? 1.f : 0.f;
    out[off + (size_t)bt * LL + threadIdx.x] =
        amask[((size_t)b * TT + node) * LL + threadIdx.x] * valid;
}
// float4 loads from aligned src; scalar stores to (possibly unaligned) dst offset
__global__ void new_emb_kernel(const float* __restrict__ emb,
                               float* __restrict__ out, long long off) {
    int bt = blockIdx.x / 48;
    int r4 = (blockIdx.x % 48) * 256 + threadIdx.x;   // float4 index within slot
    int b = bt >> 5;
    int node = g_nodefull[bt];
    float4 v = *(const float4*)(emb + ((size_t)b * TT + node) * (LL * DM) + (size_t)r4 * 4);
    float* dst = out + off + (size_t)bt * (LL * DM) + (size_t)r4 * 4;
    dst[0] = v.x; dst[1] = v.y; dst[2] = v.z; dst[3] = v.w;
}

// ---------------- host ----------------
static void run_layer(__nv_bfloat16* pW, int qkvOff, int outOff, int w1Off, int w2Off,
                      const float* qkvb, const float* outb,
                      const float* g1, const float* b1,
                      const float* c1, const float* c2,
                      const float* g2, const float* b2,
                      __nv_bfloat16* pX, __nv_bfloat16* pQKV, __nv_bfloat16* pATT,
                      __nv_bfloat16* pY, __nv_bfloat16* pHID) {
    const int GY = 248;
    mm_kernel<0><<<dim3(18, GY), 256, MM_SMEM>>>(pX, DM, pW + qkvOff, DM, qkvb, pQKV, 3 * DM, 3 * DM, DM);
    attn_kernel<<<dim3(4, 768), 256, FA_SMEM>>>(pQKV, pATT);
    mm_kernel<0><<<dim3(6, GY), 256, MM_SMEM>>>(pATT, DM, pW + outOff, DM, outb, pY, DM, DM, DM);
    add_ln_kernel<<<NMAX * LL, 256>>>(pX, pY, g1, b1);
    mm_kernel<1><<<dim3(16, GY), 256, MM_SMEM>>>(pX, DM, pW + w1Off, DM, c1, pHID, FF, FF, DM);
    mm_kernel<0><<<dim3(6, GY), 256, MM_SMEM>>>(pHID, FF, pW + w2Off, FF, c2, pY, DM, DM, FF);
    add_ln_kernel<<<NMAX * LL, 256>>>(pX, pY, g2, b2);
}

extern "C" void kernel_launch(void* const* d_in, const int* in_sizes, int n_in,
                              void* d_out, int out_size) {
    const int*   tree_lens = (const int*)d_in[0];
    const float* emb       = (const float*)d_in[1];
    const float* amask     = (const float*)d_in[2];
    const float* P[28];
    for (int i = 3; i < 31; i++) P[i - 3] = (const float*)d_in[i];
    float* out = (float*)d_out;

    __nv_bfloat16 *pX, *pQKV, *pATT, *pY, *pHID, *pZ, *pW;
    cudaGetSymbolAddress((void**)&pX, g_Xbf);
    cudaGetSymbolAddress((void**)&pQKV, g_QKVbf);
    cudaGetSymbolAddress((void**)&pATT, g_ATTbf);
    cudaGetSymbolAddress((void**)&pY, g_Ybf);
    cudaGetSymbolAddress((void**)&pHID, g_HIDbf);
    cudaGetSymbolAddress((void**)&pZ, g_Zbf);
    cudaGetSymbolAddress((void**)&pW, g_Wbf);

    cudaFuncSetAttribute(attn_kernel, cudaFuncAttributeMaxDynamicSharedMemorySize, FA_SMEM);
    cudaFuncSetAttribute(mm_kernel<0>, cudaFuncAttributeMaxDynamicSharedMemorySize, MM_SMEM);
    cudaFuncSetAttribute(mm_kernel<1>, cudaFuncAttributeMaxDynamicSharedMemorySize, MM_SMEM);
    cudaFuncSetAttribute(mm_kernel<2>, cudaFuncAttributeMaxDynamicSharedMemorySize, MM_SMEM);

    const long long NE_ELEMS = (long long)BB * TT * LL * DM;
    const long long TOT_W = 512 + 32768 + 1 + 16 + NE_ELEMS + 32768;
    int has_sc = ((long long)out_size == TOT_W - 1) ? 0 : 1;
    long long off_oh = 0;
    long long off_em = 512;
    long long off_sc = 512 + 32768;
    long long off_tl = off_sc + (has_sc ? 1 : 0);
    long long off_ne = off_tl + 16;
    long long off_nm = off_ne + NE_ELEMS;

    setup_kernel<<<1, 32>>>(tree_lens);
    gather_kernel<<<dim3(NMAX, LL), 256>>>(emb, amask);
    meanE_kernel<<<dim3(NMAX, 3), 256>>>(emb);

    conv_kernel<<<1024, 256>>>((const float4*)P[0],  (__nv_bfloat162*)(pW + OFF_EQKV), SZ_QKV / 4);
    conv_kernel<<<1024, 256>>>((const float4*)P[2],  (__nv_bfloat162*)(pW + OFF_EOUT), SZ_OUT / 4);
    conv_kernel<<<1024, 256>>>((const float4*)P[6],  (__nv_bfloat162*)(pW + OFF_EW1),  SZ_W1 / 4);
    conv_kernel<<<1024, 256>>>((const float4*)P[8],  (__nv_bfloat162*)(pW + OFF_EW2),  SZ_W2 / 4);
    conv_kernel<<<1024, 256>>>((const float4*)P[12], (__nv_bfloat162*)(pW + OFF_DQKV), SZ_QKV / 4);
    conv_kernel<<<1024, 256>>>((const float4*)P[14], (__nv_bfloat162*)(pW + OFF_DOUT), SZ_OUT / 4);
    conv_kernel<<<1024, 256>>>((const float4*)P[18], (__nv_bfloat162*)(pW + OFF_DW1),  SZ_W1 / 4);
    conv_kernel<<<1024, 256>>>((const float4*)P[20], (__nv_bfloat162*)(pW + OFF_DW2),  SZ_W2 / 4);
    conv_kernel<<<128, 256>>>((const float4*)P[24],  (__nv_bfloat162*)(pW + OFF_PE),   SZ_PE / 4);
    conv_pad_kernel<<<(DM * 128 + 255) / 256, 256>>>(P[26], pW + OFF_PD);

    const int LQKV = 3 * DM * DM, LOUT = DM * DM, LW1 = FF * DM, LW2 = DM * FF;
    for (int i = 0; i < 2; i++)
        run_layer(pW, OFF_EQKV + i * LQKV, OFF_EOUT + i * LOUT,
                  OFF_EW1 + i * LW1, OFF_EW2 + i * LW2,
                  P[1] + (size_t)i * 3 * DM, P[3] + (size_t)i * DM,
                  P[4] + (size_t)i * DM, P[5] + (size_t)i * DM,
                  P[7] + (size_t)i * FF, P[9] + (size_t)i * DM,
                  P[10] + (size_t)i * DM, P[11] + (size_t)i * DM,
                  pX, pQKV, pATT, pY, pHID);

    mm_kernel<2><<<dim3(1, 248), 256, MM_SMEM>>>(pX, DM, pW + OFF_PE, DM, P[25], pZ, 128, ZZ, DM);
    mm_kernel<2><<<dim3(6, 248), 256, MM_SMEM>>>(pZ, 128, pW + OFF_PD, 128, P[27], pX, DM, DM, 128);

    for (int i = 0; i < 2; i++)
        run_layer(pW, OFF_DQKV + i * LQKV, OFF_DOUT + i * LOUT,
                  OFF_DW1 + i * LW1, OFF_DW2 + i * LW2,
                  P[13] + (size_t)i * 3 * DM, P[15] + (size_t)i * DM,
                  P[16] + (size_t)i * DM, P[17] + (size_t)i * DM,
                  P[19] + (size_t)i * FF, P[21] + (size_t)i * DM,
                  P[22] + (size_t)i * DM, P[23] + (size_t)i * DM,
                  pX, pQKV, pATT, pY, pHID);

    anomaly_kernel<<<NMAX, 256>>>();
    select_kernel<<<1, 32>>>();

    out_small_kernel<<<3, 256>>>(out, off_oh, off_sc, off_tl, has_sc);
    ext_mask_kernel<<<BB * TT, LL>>>(out, off_em);
    new_msk_kernel<<<BB * TT, LL>>>(amask, out, off_nm);
    new_emb_kernel<<<BB * TT * 48, 256>>>(emb, out, off_ne);
}

// round 11
// speedup vs baseline: 1.3273x; 1.0659x over previous
#include <cuda_runtime.h>
#include <cuda_bf16.h>
#include <math.h>
#include <stdint.h>

#define BB   16
#define TT   32
#define LL   64
#define DM   768
#define HH   12
#define HD   64
#define FF   2048
#define ZZ   100
#define NMAX 496
#define MROWS (NMAX * LL)

// ---------------- helpers ----------------
__device__ __forceinline__ uint32_t smem_u32(const void* p) {
    uint32_t a;
    asm("{ .reg .u64 t; cvta.to.shared.u64 t, %1; cvt.u32.u64 %0, t; }" : "=r"(a) : "l"(p));
    return a;
}
__device__ __forceinline__ void cp16(uint32_t dst, const void* src) {
    asm volatile("cp.async.cg.shared.global [%0], [%1], 16;" :: "r"(dst), "l"(src));
}
__device__ __forceinline__ void cp_commit() { asm volatile("cp.async.commit_group;" ::: "memory"); }
__device__ __forceinline__ void cp_wait0()  { asm volatile("cp.async.wait_group 0;" ::: "memory"); }
__device__ __forceinline__ void cp_wait1()  { asm volatile("cp.async.wait_group 1;" ::: "memory"); }
__device__ __forceinline__ void cp_wait2()  { asm volatile("cp.async.wait_group 2;" ::: "memory"); }
__device__ __forceinline__ void ldmx4(uint32_t& r0, uint32_t& r1, uint32_t& r2, uint32_t& r3,
                                      uint32_t addr) {
    asm volatile("ldmatrix.sync.aligned.m8n8.x4.shared.b16 {%0,%1,%2,%3}, [%4];"
                 : "=r"(r0), "=r"(r1), "=r"(r2), "=r"(r3) : "r"(addr));
}
__device__ __forceinline__ void ldmx4t(uint32_t& r0, uint32_t& r1, uint32_t& r2, uint32_t& r3,
                                       uint32_t addr) {
    asm volatile("ldmatrix.sync.aligned.m8n8.x4.trans.shared.b16 {%0,%1,%2,%3}, [%4];"
                 : "=r"(r0), "=r"(r1), "=r"(r2), "=r"(r3) : "r"(addr));
}
__device__ __forceinline__ void mma16816(float* c, const uint32_t* a, const uint32_t* b) {
    asm volatile("mma.sync.aligned.m16n8k16.row.col.f32.bf16.bf16.f32 "
                 "{%0,%1,%2,%3}, {%4,%5,%6,%7}, {%8,%9}, {%0,%1,%2,%3};"
                 : "+f"(c[0]), "+f"(c[1]), "+f"(c[2]), "+f"(c[3])
                 : "r"(a[0]), "r"(a[1]), "r"(a[2]), "r"(a[3]), "r"(b[0]), "r"(b[1]));
}
__device__ __forceinline__ int imin(int a, int b) { return a < b ? a : b; }
__device__ __forceinline__ uint32_t packbf(float x, float y) {
    uint32_t r;
    asm("cvt.rn.bf16x2.f32 %0, %1, %2;" : "=r"(r) : "f"(y), "f"(x));
    return r;
}

// fast exp on the FMA pipe; x <= 0 expected
__device__ __forceinline__ float fexp(float x) {
    float t = x * 1.44269504f;
    t = fmaxf(t, -125.0f);
    float e = floorf(t);
    float f = t - e;
    float p = 1.0f + f * (0.69314718f + f * (0.24022651f + f * (0.05550411f +
              f * (0.00961813f + f * 0.00133336f))));
    return p * __int_as_float(((int)e + 127) << 23);
}

// ---------------- device scratch ----------------
__device__ __nv_bfloat16 g_Xbf  [MROWS * DM];
__device__ __nv_bfloat16 g_QKVbf[MROWS * 3 * DM];
__device__ __nv_bfloat16 g_ATTbf[MROWS * DM];
__device__ __nv_bfloat16 g_Ybf  [MROWS * DM];
__device__ __nv_bfloat16 g_HIDbf[MROWS * FF];
__device__ __nv_bfloat16 g_Zbf  [MROWS * 128];

#define OFF_EQKV 0
#define SZ_QKV   (2 * 3 * DM * DM)
#define OFF_EOUT (OFF_EQKV + SZ_QKV)
#define SZ_OUT   (2 * DM * DM)
#define OFF_EW1  (OFF_EOUT + SZ_OUT)
#define SZ_W1    (2 * FF * DM)
#define OFF_EW2  (OFF_EW1 + SZ_W1)
#define SZ_W2    (2 * DM * FF)
#define OFF_DQKV (OFF_EW2 + SZ_W2)
#define OFF_DOUT (OFF_DQKV + SZ_QKV)
#define OFF_DW1  (OFF_DOUT + SZ_OUT)
#define OFF_DW2  (OFF_DW1 + SZ_W1)
#define OFF_PE   (OFF_DW2 + SZ_W2)
#define SZ_PE    (ZZ * DM)
#define OFF_PD   (OFF_PE + SZ_PE)
#define SZ_PD    (DM * 128)
#define WPOOL_SZ (OFF_PD + SZ_PD)
__device__ __nv_bfloat16 g_Wbf[WPOOL_SZ];

__device__ float g_MSK[NMAX * LL];
__device__ float g_meanE[NMAX * DM];
__device__ float g_s[NMAX];
__device__ int   g_Ntot;
__device__ int   g_nresp[BB];
__device__ int   g_next[BB];
__device__ int   g_bidx[NMAX];
__device__ int   g_tidx[NMAX];
__device__ int   g_nodefull[BB * TT];
__device__ int   g_oh[BB * TT];

// ---------------- setup / gather ----------------
__global__ void setup_kernel(const int* __restrict__ tree_lens) {
    if (threadIdx.x == 0 && blockIdx.x == 0) {
        int tot = 0;
        for (int b = 0; b < BB; b++) {
            int tl = tree_lens[b];
            int nr = tl - 1;
            g_nresp[b] = nr;
            int ne = (int)floor((double)nr * 0.05);
            if (ne < 1) ne = 1;
            g_next[b] = ne;
            for (int j = 1; j < tl; j++) { g_bidx[tot] = b; g_tidx[tot] = j; tot++; }
        }
        g_Ntot = tot;
    }
}

// float4 loads, 4xbf16 (uint2) stores; 192 threads cover 768 elems
__global__ void gather_kernel(const float* __restrict__ emb, const float* __restrict__ amask) {
    int n = blockIdx.x, l = blockIdx.y;
    if (n >= g_Ntot) return;
    int bi = g_bidx[n], ti = g_tidx[n];
    const float4* src = (const float4*)(emb + (((size_t)bi * TT + ti) * LL + l) * DM);
    __nv_bfloat16* dst = g_Xbf + ((size_t)n * LL + l) * DM;
    int t = threadIdx.x;  // 192
    float4 v = src[t];
    uint2 o;
    o.x = packbf(v.x, v.y);
    o.y = packbf(v.z, v.w);
    *(uint2*)(dst + t * 4) = o;
    if (t == 0)
        g_MSK[n * LL + l] = amask[((size_t)bi * TT + ti) * LL + l];
}

__global__ void meanE_kernel(const float* __restrict__ emb) {
    int n = blockIdx.x;
    if (n >= g_Ntot) return;
    int d = blockIdx.y * 256 + threadIdx.x;
    int bi = g_bidx[n], ti = g_tidx[n];
    const float* base = emb + ((size_t)bi * TT + ti) * LL * DM;
    float s = 0.f;
    for (int l = 0; l < LL; l++) s += base[(size_t)l * DM + d];
    g_meanE[n * DM + d] = s * (1.f / (float)LL);
}

// ---------------- weight converts (vectorized) ----------------
__global__ void conv_kernel(const float4* __restrict__ src, __nv_bfloat162* __restrict__ dst,
                            int cnt4) {
    for (int i = blockIdx.x * blockDim.x + threadIdx.x; i < cnt4; i += gridDim.x * blockDim.x) {
        float4 v = src[i];
        dst[2 * i]     = __floats2bfloat162_rn(v.x, v.y);
        dst[2 * i + 1] = __floats2bfloat162_rn(v.z, v.w);
    }
}
__global__ void conv_pad_kernel(const float* __restrict__ src, __nv_bfloat16* __restrict__ dst) {
    int i = blockIdx.x * blockDim.x + threadIdx.x;
    if (i >= DM * 128) return;
    int r = i >> 7, c = i & 127;
    dst[i] = __float2bfloat16((c < ZZ) ? src[r * ZZ + c] : 0.f);
}

// ---------------- warp-MMA GEMM: 128x128x32 block, 8 warps, warp tile 32x64 ----------------
#define MM_SMEM (4 * (128 * 40 + 128 * 40) * 2)   // 81920 bytes

template <int MODE>
__global__ void __launch_bounds__(256, 2) mm_kernel(
    const __nv_bfloat16* __restrict__ A, long long sAi,
    const __nv_bfloat16* __restrict__ B, long long sBi,
    const float* __restrict__ bias,
    __nv_bfloat16* __restrict__ C, long long sCi,
    int Nreal, int Kdim)
{
    int Mreal = g_Ntot * LL;
    int m0 = blockIdx.y * 128;
    if (m0 >= Mreal) return;
    int n0 = blockIdx.x * 128;
    size_t stA = (size_t)sAi, stB = (size_t)sBi;
    int Ktiles = Kdim >> 5;

    extern __shared__ __nv_bfloat16 sm[];
    __nv_bfloat16* As = sm;
    __nv_bfloat16* Bs = sm + 4 * 128 * 40;

    int tid = threadIdx.x;
    int lane = tid & 31;
    int w = tid >> 5;
    int wm = w >> 1;
    int wn = w & 1;

    float acc[2][8][4];
#pragma unroll
    for (int i = 0; i < 2; i++)
#pragma unroll
        for (int j = 0; j < 8; j++)
#pragma unroll
            for (int q = 0; q < 4; q++) acc[i][j][q] = 0.f;

    auto load_tile = [&](int kt, int s) {
        __nv_bfloat16* as = As + s * 128 * 40;
        __nv_bfloat16* bs = Bs + s * 128 * 40;
#pragma unroll
        for (int i = 0; i < 2; i++) {
            int c = tid + i * 256;
            int r = c >> 2, ko = (c & 3) * 8;
            int m = imin(m0 + r, Mreal - 1);
            cp16(smem_u32(&as[r * 40 + ko]), A + (size_t)m * stA + (size_t)kt * 32 + ko);
        }
#pragma unroll
        for (int i = 0; i < 2; i++) {
            int c = tid + i * 256;
            int r = c >> 2, ko = (c & 3) * 8;
            int n = imin(n0 + r, Nreal - 1);
            cp16(smem_u32(&bs[r * 40 + ko]), B + (size_t)n * stB + (size_t)kt * 32 + ko);
        }
    };

    load_tile(0, 0); cp_commit();
    if (Ktiles > 1) load_tile(1, 1);
    cp_commit();

    for (int kt = 0; kt < Ktiles; kt++) {
        if (kt + 2 < Ktiles) load_tile(kt + 2, (kt + 2) & 3);
        cp_commit();
        cp_wait2();
        __syncthreads();

        int s = kt & 3;
        const __nv_bfloat16* as = As + s * 128 * 40;
        const __nv_bfloat16* bs = Bs + s * 128 * 40;
#pragma unroll
        for (int ks = 0; ks < 2; ks++) {
            int k0 = ks * 16;
            uint32_t a[2][4], bb[8][2];
#pragma unroll
            for (int mf = 0; mf < 2; mf++) {
                int row = wm * 32 + mf * 16 + (lane & 7) + ((lane >> 3) & 1) * 8;
                int col = k0 + (lane >> 4) * 8;
                ldmx4(a[mf][0], a[mf][1], a[mf][2], a[mf][3], smem_u32(&as[row * 40 + col]));
            }
#pragma unroll
            for (int ng = 0; ng < 4; ng++) {
                int row = wn * 64 + ng * 16 + (lane & 7) + (lane >> 4) * 8;
                int col = k0 + ((lane >> 3) & 1) * 8;
                uint32_t r0, r1, r2, r3;
                ldmx4(r0, r1, r2, r3, smem_u32(&bs[row * 40 + col]));
                bb[ng * 2][0] = r0;     bb[ng * 2][1] = r1;
                bb[ng * 2 + 1][0] = r2; bb[ng * 2 + 1][1] = r3;
            }
#pragma unroll
            for (int mf = 0; mf < 2; mf++)
#pragma unroll
                for (int nf = 0; nf < 8; nf++)
                    mma16816(acc[mf][nf], a[mf], bb[nf]);
        }
    }

    int width = (int)sCi;
#pragma unroll
    for (int mf = 0; mf < 2; mf++) {
#pragma unroll
        for (int nf = 0; nf < 8; nf++) {
            int rbase = m0 + wm * 32 + mf * 16 + (lane >> 2);
            int cbase = n0 + wn * 64 + nf * 8 + (lane & 3) * 2;
            if (cbase >= width) continue;
#pragma unroll
            for (int q = 0; q < 2; q++) {
                int m = rbase + q * 8;
                if (m >= Mreal) continue;
                float v0 = (cbase < Nreal)     ? acc[mf][nf][q * 2]     + bias[cbase]     : 0.f;
                float v1 = (cbase + 1 < Nreal) ? acc[mf][nf][q * 2 + 1] + bias[cbase + 1] : 0.f;
                if (MODE == 1) { v0 = fmaxf(v0, 0.f); v1 = fmaxf(v1, 0.f); }
                if (MODE == 2) { v0 = tanhf(v0); v1 = tanhf(v1); }
                *(__nv_bfloat162*)(C + (size_t)m * width + cbase) = __floats2bfloat162_rn(v0, v1);
            }
        }
    }
}

// ---------------- flash attention: single pass, online softmax in registers ----------------
#define FA_Q   0
#define FA_K   (128 * 72 * 2)
#define FA_V   (FA_K + 2 * 64 * 72 * 2)
#define FA_MSK (FA_V + 2 * 64 * 72 * 2)
#define FA_SMEM (FA_MSK + 512 * 4)

__global__ void __launch_bounds__(256) attn_kernel(
    const __nv_bfloat16* __restrict__ QKV, __nv_bfloat16* __restrict__ ATT)
{
    int Nt = g_Ntot;
    int n0 = blockIdx.x * 128;
    if (n0 >= Nt) return;
    int z = blockIdx.y;
    int l = z / HH, h = z % HH;
    int Mtiles = (Nt + 63) >> 6;

    extern __shared__ char smem[];
    __nv_bfloat16* Qs = (__nv_bfloat16*)(smem + FA_Q);
    __nv_bfloat16* Ks = (__nv_bfloat16*)(smem + FA_K);
    __nv_bfloat16* Vs = (__nv_bfloat16*)(smem + FA_V);
    float*        msk = (float*)(smem + FA_MSK);

    int tid = threadIdx.x;
    int lane = tid & 31;
    int w = tid >> 5;

    for (int j = tid; j < 512; j += 256)
        msk[j] = (j < Nt) ? g_MSK[j * LL + l] : -1e30f;

#pragma unroll
    for (int i = 0; i < 4; i++) {
        int c = tid + i * 256;
        int r = c >> 3, co = (c & 7) * 8;
        int n = imin(n0 + r, Nt - 1);
        cp16(smem_u32(&Qs[r * 72 + co]), QKV + ((size_t)n * LL + l) * (3 * DM) + h * HD + co);
    }
    cp_commit();

    auto load_kv = [&](int mt, int buf) {
#pragma unroll
        for (int i = 0; i < 2; i++) {
            int c = tid + i * 256;
            int r = c >> 3, co = (c & 7) * 8;
            int m = imin(mt * 64 + r, Nt - 1);
            const __nv_bfloat16* base = QKV + ((size_t)m * LL + l) * (3 * DM) + h * HD + co;
            cp16(smem_u32(&Ks[(buf * 64 + r) * 72 + co]), base + DM);
            cp16(smem_u32(&Vs[(buf * 64 + r) * 72 + co]), base + 2 * DM);
        }
    };

    load_kv(0, 0);
    cp_commit();
    cp_wait1();
    __syncthreads();

    uint32_t aq[4][4];
#pragma unroll
    for (int ks = 0; ks < 4; ks++) {
        int row = w * 16 + (lane & 7) + ((lane >> 3) & 1) * 8;
        int col = ks * 16 + (lane >> 4) * 8;
        ldmx4(aq[ks][0], aq[ks][1], aq[ks][2], aq[ks][3], smem_u32(&Qs[row * 72 + col]));
    }

    float oacc[8][4];
#pragma unroll
    for (int j = 0; j < 8; j++)
#pragma unroll
        for (int q = 0; q < 4; q++) oacc[j][q] = 0.f;
    float mrow[2] = { -1e30f, -1e30f };
    float lrow[2] = { 0.f, 0.f };

    for (int mt = 0; mt < Mtiles; mt++) {
        int buf = mt & 1;
        if (mt + 1 < Mtiles) { load_kv(mt + 1, buf ^ 1); cp_commit(); cp_wait1(); }
        else cp_wait0();
        __syncthreads();

        float sacc[8][4];
#pragma unroll
        for (int j = 0; j < 8; j++)
#pragma unroll
            for (int q = 0; q < 4; q++) sacc[j][q] = 0.f;

#pragma unroll
        for (int ks = 0; ks < 4; ks++) {
            uint32_t bb[8][2];
#pragma unroll
            for (int ng = 0; ng < 4; ng++) {
                int row = ng * 16 + (lane & 7) + (lane >> 4) * 8;
                int col = ks * 16 + ((lane >> 3) & 1) * 8;
                uint32_t r0, r1, r2, r3;
                ldmx4(r0, r1, r2, r3, smem_u32(&Ks[(buf * 64 + row) * 72 + col]));
                bb[ng * 2][0] = r0;     bb[ng * 2][1] = r1;
                bb[ng * 2 + 1][0] = r2; bb[ng * 2 + 1][1] = r3;
            }
#pragma unroll
            for (int nf = 0; nf < 8; nf++) mma16816(sacc[nf], aq[ks], bb[nf]);
        }

#pragma unroll
        for (int nf = 0; nf < 8; nf++) {
            int kc = mt * 64 + nf * 8 + (lane & 3) * 2;
            float mk0 = msk[kc], mk1 = msk[kc + 1];
            sacc[nf][0] = sacc[nf][0] * 0.125f + mk0;
            sacc[nf][1] = sacc[nf][1] * 0.125f + mk1;
            sacc[nf][2] = sacc[nf][2] * 0.125f + mk0;
            sacc[nf][3] = sacc[nf][3] * 0.125f + mk1;
        }

#pragma unroll
        for (int q = 0; q < 2; q++) {
            float tm = -1e30f;
#pragma unroll
            for (int nf = 0; nf < 8; nf++)
                tm = fmaxf(tm, fmaxf(sacc[nf][q * 2], sacc[nf][q * 2 + 1]));
            tm = fmaxf(tm, __shfl_xor_sync(0xffffffff, tm, 1));
            tm = fmaxf(tm, __shfl_xor_sync(0xffffffff, tm, 2));
            float mnew = fmaxf(mrow[q], tm);
            float sc = fexp(mrow[q] - mnew);
            float tsum = 0.f;
#pragma unroll
            for (int nf = 0; nf < 8; nf++) {
                float p0 = fexp(sacc[nf][q * 2]     - mnew);
                float p1 = fexp(sacc[nf][q * 2 + 1] - mnew);
                sacc[nf][q * 2] = p0; sacc[nf][q * 2 + 1] = p1;
                tsum += p0 + p1;
            }
            tsum += __shfl_xor_sync(0xffffffff, tsum, 1);
            tsum += __shfl_xor_sync(0xffffffff, tsum, 2);
            lrow[q] = lrow[q] * sc + tsum;
            mrow[q] = mnew;
#pragma unroll
            for (int nf = 0; nf < 8; nf++) {
                oacc[nf][q * 2]     *= sc;
                oacc[nf][q * 2 + 1] *= sc;
            }
        }

#pragma unroll
        for (int ks = 0; ks < 4; ks++) {
            uint32_t ap[4];
            ap[0] = packbf(sacc[2 * ks][0],     sacc[2 * ks][1]);
            ap[1] = packbf(sacc[2 * ks][2],     sacc[2 * ks][3]);
            ap[2] = packbf(sacc[2 * ks + 1][0], sacc[2 * ks + 1][1]);
            ap[3] = packbf(sacc[2 * ks + 1][2], sacc[2 * ks + 1][3]);
            uint32_t vb[8][2];
#pragma unroll
            for (int ng = 0; ng < 4; ng++) {
                int vrow = ks * 16 + (lane & 7) + ((lane >> 3) & 1) * 8;
                int vcol = ng * 16 + (lane >> 4) * 8;
                uint32_t r0, r1, r2, r3;
                ldmx4t(r0, r1, r2, r3, smem_u32(&Vs[(buf * 64 + vrow) * 72 + vcol]));
                vb[ng * 2][0] = r0;     vb[ng * 2][1] = r1;
                vb[ng * 2 + 1][0] = r2; vb[ng * 2 + 1][1] = r3;
            }
#pragma unroll
            for (int nf = 0; nf < 8; nf++) mma16816(oacc[nf], ap, vb[nf]);
        }
        __syncthreads();
    }

    float inv0 = 1.f / lrow[0];
    float inv1 = 1.f / lrow[1];
#pragma unroll
    for (int nf = 0; nf < 8; nf++) {
        int c = nf * 8 + (lane & 3) * 2;
#pragma unroll
        for (int q = 0; q < 2; q++) {
            int n = n0 + w * 16 + (lane >> 2) + q * 8;
            if (n < Nt) {
                float inv = q ? inv1 : inv0;
                __nv_bfloat16* row = ATT + ((size_t)n * LL + l) * DM + h * HD + c;
                *(__nv_bfloat162*)row =
                    __floats2bfloat162_rn(oacc[nf][q * 2] * inv, oacc[nf][q * 2 + 1] * inv);
            }
        }
    }
}

// ---------------- residual + LayerNorm: warp per row, uint4 loads, shfl reduce ----------------
__global__ void __launch_bounds__(256) add_ln_kernel(
    __nv_bfloat16* __restrict__ X, const __nv_bfloat16* __restrict__ Yv,
    const float* __restrict__ g, const float* __restrict__ b) {
    int row = blockIdx.x * 8 + (threadIdx.x >> 5);
    if (row >= g_Ntot * LL) return;
    int lane = threadIdx.x & 31;
    __nv_bfloat16* x = X + (size_t)row * DM;
    const __nv_bfloat16* y = Yv + (size_t)row * DM;

    float v[24];
    float s = 0.f, s2 = 0.f;
#pragma unroll
    for (int i = 0; i < 3; i++) {
        int d = i * 256 + lane * 8;
        uint4 xv = *(const uint4*)(x + d);
        uint4 yv = *(const uint4*)(y + d);
        const __nv_bfloat162* xp = (const __nv_bfloat162*)&xv;
        const __nv_bfloat162* yp = (const __nv_bfloat162*)&yv;
#pragma unroll
        for (int j = 0; j < 4; j++) {
            float2 xf = __bfloat1622float2(xp[j]);
            float2 yf = __bfloat1622float2(yp[j]);
            float u0 = xf.x + yf.x, u1 = xf.y + yf.y;
            v[i * 8 + j * 2] = u0; v[i * 8 + j * 2 + 1] = u1;
            s += u0 + u1; s2 += u0 * u0 + u1 * u1;
        }
    }
#pragma unroll
    for (int o = 16; o > 0; o >>= 1) {
        s  += __shfl_xor_sync(0xffffffff, s, o);
        s2 += __shfl_xor_sync(0xffffffff, s2, o);
    }
    float mean = s * (1.f / (float)DM);
    float var = s2 * (1.f / (float)DM) - mean * mean;
    float inv = rsqrtf(var + 1e-5f);
#pragma unroll
    for (int i = 0; i < 3; i++) {
        int d = i * 256 + lane * 8;
        float4 g0 = *(const float4*)(g + d);
        float4 g1 = *(const float4*)(g + d + 4);
        float4 b0 = *(const float4*)(b + d);
        float4 b1 = *(const float4*)(b + d + 4);
        uint4 ov;
        uint32_t* op = (uint32_t*)&ov;
        const float* gp0 = (const float*)&g0;
        const float* gp1 = (const float*)&g1;
        const float* bp0 = (const float*)&b0;
        const float* bp1 = (const float*)&b1;
#pragma unroll
        for (int j = 0; j < 2; j++) {
            float r0 = (v[i * 8 + j * 2]     - mean) * inv * gp0[j * 2]     + bp0[j * 2];
            float r1 = (v[i * 8 + j * 2 + 1] - mean) * inv * gp0[j * 2 + 1] + bp0[j * 2 + 1];
            op[j] = packbf(r0, r1);
        }
#pragma unroll
        for (int j = 0; j < 2; j++) {
            float r0 = (v[i * 8 + 4 + j * 2]     - mean) * inv * gp1[j * 2]     + bp1[j * 2];
            float r1 = (v[i * 8 + 4 + j * 2 + 1] - mean) * inv * gp1[j * 2 + 1] + bp1[j * 2 + 1];
            op[2 + j] = packbf(r0, r1);
        }
        *(uint4*)(x + d) = ov;
    }
}

// ---------------- anomaly ----------------
__global__ void anomaly_kernel() {
    int n = blockIdx.x;
    if (n >= g_Ntot) return;
    int t = threadIdx.x;
    float acc = 0.f;
#pragma unroll
    for (int i = 0; i < 3; i++) {
        int d = t + 256 * i;
        float m = 0.f;
        for (int l = 0; l < LL; l++)
            m += __bfloat162float(g_Xbf[((size_t)n * LL + l) * DM + d]);
        m *= (1.f / (float)LL);
        float diff = m - g_meanE[n * DM + d];
        acc += diff * diff;
    }
    __shared__ float red[256];
    red[t] = acc; __syncthreads();
    for (int s = 128; s > 0; s >>= 1) { if (t < s) red[t] += red[t + s]; __syncthreads(); }
    if (t == 0) g_s[n] = red[0];
}

// ---------------- selection ----------------
__global__ void select_kernel() {
    int b = threadIdx.x;
    if (b >= BB) return;
    int nr = g_nresp[b];
    int ne = g_next[b];
    bool used[TT];
    int ohf[TT];
#pragma unroll
    for (int j = 0; j < TT; j++) { used[j] = false; ohf[j] = 0; }
    ohf[0] = 1;
    g_nodefull[b * TT + 0] = 0;
    for (int i = 0; i < TT - 1; i++) {
        int node = 0;
        if (i < ne) {
            float best = INFINITY; int bj = 0;
            for (int j = 0; j < nr; j++) {
                if (!used[j] && g_s[j] < best) { best = g_s[j]; bj = j; }
            }
            used[bj] = true;
            node = bj + 1;
            ohf[node] = 1;
        }
        g_nodefull[b * TT + i + 1] = node;
    }
    for (int t = 0; t < TT; t++) g_oh[b * TT + t] = ohf[t];
}

// ---------------- output writers ----------------
__global__ void out_small_kernel(float* __restrict__ out, long long off_oh,
                                 long long off_sc, long long off_tl, int has_sc) {
    int t = blockIdx.x * blockDim.x + threadIdx.x;
    if (t < BB * TT) out[off_oh + t] = (float)g_oh[t];
    else if (t < BB * TT + BB) out[off_tl + (t - BB * TT)] = (float)(1 + g_next[t - BB * TT]);
    else if (t == BB * TT + BB && has_sc) out[off_sc] = 0.f;
}
__global__ void ext_mask_kernel(float* __restrict__ out, long long off) {
    int bt = blockIdx.x;
    out[off + (size_t)bt * LL + threadIdx.x] = (float)g_oh[bt];
}
__global__ void new_msk_kernel(const float* __restrict__ amask,
                               float* __restrict__ out, long long off) {
    int bt = blockIdx.x;
    int b = bt >> 5, t = bt & 31;
    int node = g_nodefull[bt];
    float valid = (t == 0 || (t - 1) < g_next[b]) ? 1.f : 0.f;
    out[off + (size_t)bt * LL + threadIdx.x] =
        amask[((size_t)b * TT + node) * LL + threadIdx.x] * valid;
}
// float4 loads from aligned src; scalar stores to (possibly unaligned) dst offset
__global__ void new_emb_kernel(const float* __restrict__ emb,
                               float* __restrict__ out, long long off) {
    int bt = blockIdx.x / 48;
    int r4 = (blockIdx.x % 48) * 256 + threadIdx.x;
    int b = bt >> 5;
    int node = g_nodefull[bt];
    float4 v = *(const float4*)(emb + ((size_t)b * TT + node) * (LL * DM) + (size_t)r4 * 4);
    float* dst = out + off + (size_t)bt * (LL * DM) + (size_t)r4 * 4;
    dst[0] = v.x; dst[1] = v.y; dst[2] = v.z; dst[3] = v.w;
}

// ---------------- host ----------------
static void run_layer(__nv_bfloat16* pW, int qkvOff, int outOff, int w1Off, int w2Off,
                      const float* qkvb, const float* outb,
                      const float* g1, const float* b1,
                      const float* c1, const float* c2,
                      const float* g2, const float* b2,
                      __nv_bfloat16* pX, __nv_bfloat16* pQKV, __nv_bfloat16* pATT,
                      __nv_bfloat16* pY, __nv_bfloat16* pHID) {
    const int GY = 248;
    const int LNB = (NMAX * LL + 7) / 8;  // 3968
    mm_kernel<0><<<dim3(18, GY), 256, MM_SMEM>>>(pX, DM, pW + qkvOff, DM, qkvb, pQKV, 3 * DM, 3 * DM, DM);
    attn_kernel<<<dim3(4, 768), 256, FA_SMEM>>>(pQKV, pATT);
    mm_kernel<0><<<dim3(6, GY), 256, MM_SMEM>>>(pATT, DM, pW + outOff, DM, outb, pY, DM, DM, DM);
    add_ln_kernel<<<LNB, 256>>>(pX, pY, g1, b1);
    mm_kernel<1><<<dim3(16, GY), 256, MM_SMEM>>>(pX, DM, pW + w1Off, DM, c1, pHID, FF, FF, DM);
    mm_kernel<0><<<dim3(6, GY), 256, MM_SMEM>>>(pHID, FF, pW + w2Off, FF, c2, pY, DM, DM, FF);
    add_ln_kernel<<<LNB, 256>>>(pX, pY, g2, b2);
}

extern "C" void kernel_launch(void* const* d_in, const int* in_sizes, int n_in,
                              void* d_out, int out_size) {
    const int*   tree_lens = (const int*)d_in[0];
    const float* emb       = (const float*)d_in[1];
    const float* amask     = (const float*)d_in[2];
    const float* P[28];
    for (int i = 3; i < 31; i++) P[i - 3] = (const float*)d_in[i];
    float* out = (float*)d_out;

    __nv_bfloat16 *pX, *pQKV, *pATT, *pY, *pHID, *pZ, *pW;
    cudaGetSymbolAddress((void**)&pX, g_Xbf);
    cudaGetSymbolAddress((void**)&pQKV, g_QKVbf);
    cudaGetSymbolAddress((void**)&pATT, g_ATTbf);
    cudaGetSymbolAddress((void**)&pY, g_Ybf);
    cudaGetSymbolAddress((void**)&pHID, g_HIDbf);
    cudaGetSymbolAddress((void**)&pZ, g_Zbf);
    cudaGetSymbolAddress((void**)&pW, g_Wbf);

    cudaFuncSetAttribute(attn_kernel, cudaFuncAttributeMaxDynamicSharedMemorySize, FA_SMEM);
    cudaFuncSetAttribute(mm_kernel<0>, cudaFuncAttributeMaxDynamicSharedMemorySize, MM_SMEM);
    cudaFuncSetAttribute(mm_kernel<1>, cudaFuncAttributeMaxDynamicSharedMemorySize, MM_SMEM);
    cudaFuncSetAttribute(mm_kernel<2>, cudaFuncAttributeMaxDynamicSharedMemorySize, MM_SMEM);

    const long long NE_ELEMS = (long long)BB * TT * LL * DM;
    const long long TOT_W = 512 + 32768 + 1 + 16 + NE_ELEMS + 32768;
    int has_sc = ((long long)out_size == TOT_W - 1) ? 0 : 1;
    long long off_oh = 0;
    long long off_em = 512;
    long long off_sc = 512 + 32768;
    long long off_tl = off_sc + (has_sc ? 1 : 0);
    long long off_ne = off_tl + 16;
    long long off_nm = off_ne + NE_ELEMS;

    setup_kernel<<<1, 32>>>(tree_lens);
    gather_kernel<<<dim3(NMAX, LL), 192>>>(emb, amask);
    meanE_kernel<<<dim3(NMAX, 3), 256>>>(emb);

    conv_kernel<<<1024, 256>>>((const float4*)P[0],  (__nv_bfloat162*)(pW + OFF_EQKV), SZ_QKV / 4);
    conv_kernel<<<1024, 256>>>((const float4*)P[2],  (__nv_bfloat162*)(pW + OFF_EOUT), SZ_OUT / 4);
    conv_kernel<<<1024, 256>>>((const float4*)P[6],  (__nv_bfloat162*)(pW + OFF_EW1),  SZ_W1 / 4);
    conv_kernel<<<1024, 256>>>((const float4*)P[8],  (__nv_bfloat162*)(pW + OFF_EW2),  SZ_W2 / 4);
    conv_kernel<<<1024, 256>>>((const float4*)P[12], (__nv_bfloat162*)(pW + OFF_DQKV), SZ_QKV / 4);
    conv_kernel<<<1024, 256>>>((const float4*)P[14], (__nv_bfloat162*)(pW + OFF_DOUT), SZ_OUT / 4);
    conv_kernel<<<1024, 256>>>((const float4*)P[18], (__nv_bfloat162*)(pW + OFF_DW1),  SZ_W1 / 4);
    conv_kernel<<<1024, 256>>>((const float4*)P[20], (__nv_bfloat162*)(pW + OFF_DW2),  SZ_W2 / 4);
    conv_kernel<<<128, 256>>>((const float4*)P[24],  (__nv_bfloat162*)(pW + OFF_PE),   SZ_PE / 4);
    conv_pad_kernel<<<(DM * 128 + 255) / 256, 256>>>(P[26], pW + OFF_PD);

    const int LQKV = 3 * DM * DM, LOUT = DM * DM, LW1 = FF * DM, LW2 = DM * FF;
    for (int i = 0; i < 2; i++)
        run_layer(pW, OFF_EQKV + i * LQKV, OFF_EOUT + i * LOUT,
                  OFF_EW1 + i * LW1, OFF_EW2 + i * LW2,
                  P[1] + (size_t)i * 3 * DM, P[3] + (size_t)i * DM,
                  P[4] + (size_t)i * DM, P[5] + (size_t)i * DM,
                  P[7] + (size_t)i * FF, P[9] + (size_t)i * DM,
                  P[10] + (size_t)i * DM, P[11] + (size_t)i * DM,
                  pX, pQKV, pATT, pY, pHID);

    mm_kernel<2><<<dim3(1, 248), 256, MM_SMEM>>>(pX, DM, pW + OFF_PE, DM, P[25], pZ, 128, ZZ, DM);
    mm_kernel<2><<<dim3(6, 248), 256, MM_SMEM>>>(pZ, 128, pW + OFF_PD, 128, P[27], pX, DM, DM, 128);

    for (int i = 0; i < 2; i++)
        run_layer(pW, OFF_DQKV + i * LQKV, OFF_DOUT + i * LOUT,
                  OFF_DW1 + i * LW1, OFF_DW2 + i * LW2,
                  P[13] + (size_t)i * 3 * DM, P[15] + (size_t)i * DM,
                  P[16] + (size_t)i * DM, P[17] + (size_t)i * DM,
                  P[19] + (size_t)i * FF, P[21] + (size_t)i * DM,
                  P[22] + (size_t)i * DM, P[23] + (size_t)i * DM,
                  pX, pQKV, pATT, pY, pHID);

    anomaly_kernel<<<NMAX, 256>>>();
    select_kernel<<<1, 32>>>();

    out_small_kernel<<<3, 256>>>(out, off_oh, off_sc, off_tl, has_sc);
    ext_mask_kernel<<<BB * TT, LL>>>(out, off_em);
    new_msk_kernel<<<BB * TT, LL>>>(amask, out, off_nm);
    new_emb_kernel<<<BB * TT * 48, 256>>>(emb, out, off_ne);
}

// round 12
// speedup vs baseline: 1.3913x; 1.0482x over previous
#include <cuda_runtime.h>
#include <cuda_bf16.h>
#include <math.h>
#include <stdint.h>

#define BB   16
#define TT   32
#define LL   64
#define DM   768
#define HH   12
#define HD   64
#define FF   2048
#define ZZ   100
#define NMAX 496
#define MROWS (NMAX * LL)

// ---------------- helpers ----------------
__device__ __forceinline__ uint32_t smem_u32(const void* p) {
    uint32_t a;
    asm("{ .reg .u64 t; cvta.to.shared.u64 t, %1; cvt.u32.u64 %0, t; }" : "=r"(a) : "l"(p));
    return a;
}
__device__ __forceinline__ void cp16(uint32_t dst, const void* src) {
    asm volatile("cp.async.cg.shared.global [%0], [%1], 16;" :: "r"(dst), "l"(src));
}
__device__ __forceinline__ void cp_commit() { asm volatile("cp.async.commit_group;" ::: "memory"); }
__device__ __forceinline__ void cp_wait0()  { asm volatile("cp.async.wait_group 0;" ::: "memory"); }
__device__ __forceinline__ void cp_wait1()  { asm volatile("cp.async.wait_group 1;" ::: "memory"); }
__device__ __forceinline__ void ldmx4(uint32_t& r0, uint32_t& r1, uint32_t& r2, uint32_t& r3,
                                      uint32_t addr) {
    asm volatile("ldmatrix.sync.aligned.m8n8.x4.shared.b16 {%0,%1,%2,%3}, [%4];"
                 : "=r"(r0), "=r"(r1), "=r"(r2), "=r"(r3) : "r"(addr));
}
__device__ __forceinline__ void ldmx4t(uint32_t& r0, uint32_t& r1, uint32_t& r2, uint32_t& r3,
                                       uint32_t addr) {
    asm volatile("ldmatrix.sync.aligned.m8n8.x4.trans.shared.b16 {%0,%1,%2,%3}, [%4];"
                 : "=r"(r0), "=r"(r1), "=r"(r2), "=r"(r3) : "r"(addr));
}
__device__ __forceinline__ void mma16816(float* c, const uint32_t* a, const uint32_t* b) {
    asm volatile("mma.sync.aligned.m16n8k16.row.col.f32.bf16.bf16.f32 "
                 "{%0,%1,%2,%3}, {%4,%5,%6,%7}, {%8,%9}, {%0,%1,%2,%3};"
                 : "+f"(c[0]), "+f"(c[1]), "+f"(c[2]), "+f"(c[3])
                 : "r"(a[0]), "r"(a[1]), "r"(a[2]), "r"(a[3]), "r"(b[0]), "r"(b[1]));
}
__device__ __forceinline__ int imin(int a, int b) { return a < b ? a : b; }
__device__ __forceinline__ uint32_t packbf(float x, float y) {
    uint32_t r;
    asm("cvt.rn.bf16x2.f32 %0, %1, %2;" : "=r"(r) : "f"(y), "f"(x));
    return r;
}

// fast exp on the FMA pipe; x <= 0 expected
__device__ __forceinline__ float fexp(float x) {
    float t = x * 1.44269504f;
    t = fmaxf(t, -125.0f);
    float e = floorf(t);
    float f = t - e;
    float p = 1.0f + f * (0.69314718f + f * (0.24022651f + f * (0.05550411f +
              f * (0.00961813f + f * 0.00133336f))));
    return p * __int_as_float(((int)e + 127) << 23);
}

// ---------------- device scratch ----------------
__device__ __nv_bfloat16 g_Xbf  [MROWS * DM];
__device__ __nv_bfloat16 g_QKVbf[MROWS * 3 * DM];
__device__ __nv_bfloat16 g_ATTbf[MROWS * DM];
__device__ __nv_bfloat16 g_Ybf  [MROWS * DM];
__device__ __nv_bfloat16 g_HIDbf[MROWS * FF];
__device__ __nv_bfloat16 g_Zbf  [MROWS * 128];

#define OFF_EQKV 0
#define SZ_QKV   (2 * 3 * DM * DM)
#define OFF_EOUT (OFF_EQKV + SZ_QKV)
#define SZ_OUT   (2 * DM * DM)
#define OFF_EW1  (OFF_EOUT + SZ_OUT)
#define SZ_W1    (2 * FF * DM)
#define OFF_EW2  (OFF_EW1 + SZ_W1)
#define SZ_W2    (2 * DM * FF)
#define OFF_DQKV (OFF_EW2 + SZ_W2)
#define OFF_DOUT (OFF_DQKV + SZ_QKV)
#define OFF_DW1  (OFF_DOUT + SZ_OUT)
#define OFF_DW2  (OFF_DW1 + SZ_W1)
#define OFF_PE   (OFF_DW2 + SZ_W2)
#define SZ_PE    (ZZ * DM)
#define OFF_PD   (OFF_PE + SZ_PE)
#define SZ_PD    (DM * 128)
#define WPOOL_SZ (OFF_PD + SZ_PD)
__device__ __nv_bfloat16 g_Wbf[WPOOL_SZ];

__device__ float g_MSK[NMAX * LL];
__device__ float g_meanE[NMAX * DM];
__device__ float g_s[NMAX];
__device__ int   g_Ntot;
__device__ int   g_nresp[BB];
__device__ int   g_next[BB];
__device__ int   g_bidx[NMAX];
__device__ int   g_tidx[NMAX];
__device__ int   g_nodefull[BB * TT];
__device__ int   g_oh[BB * TT];

// ---------------- setup / gather ----------------
__global__ void setup_kernel(const int* __restrict__ tree_lens) {
    if (threadIdx.x == 0 && blockIdx.x == 0) {
        int tot = 0;
        for (int b = 0; b < BB; b++) {
            int tl = tree_lens[b];
            int nr = tl - 1;
            g_nresp[b] = nr;
            int ne = (int)floor((double)nr * 0.05);
            if (ne < 1) ne = 1;
            g_next[b] = ne;
            for (int j = 1; j < tl; j++) { g_bidx[tot] = b; g_tidx[tot] = j; tot++; }
        }
        g_Ntot = tot;
    }
}

__global__ void gather_kernel(const float* __restrict__ emb, const float* __restrict__ amask) {
    int n = blockIdx.x, l = blockIdx.y;
    if (n >= g_Ntot) return;
    int bi = g_bidx[n], ti = g_tidx[n];
    const float4* src = (const float4*)(emb + (((size_t)bi * TT + ti) * LL + l) * DM);
    __nv_bfloat16* dst = g_Xbf + ((size_t)n * LL + l) * DM;
    int t = threadIdx.x;  // 192
    float4 v = src[t];
    uint2 o;
    o.x = packbf(v.x, v.y);
    o.y = packbf(v.z, v.w);
    *(uint2*)(dst + t * 4) = o;
    if (t == 0)
        g_MSK[n * LL + l] = amask[((size_t)bi * TT + ti) * LL + l];
}

__global__ void meanE_kernel(const float* __restrict__ emb) {
    int n = blockIdx.x;
    if (n >= g_Ntot) return;
    int d = blockIdx.y * 256 + threadIdx.x;
    int bi = g_bidx[n], ti = g_tidx[n];
    const float* base = emb + ((size_t)bi * TT + ti) * LL * DM;
    float s = 0.f;
    for (int l = 0; l < LL; l++) s += base[(size_t)l * DM + d];
    g_meanE[n * DM + d] = s * (1.f / (float)LL);
}

// ---------------- fused weight convert (all 9 full regions, one launch) ----------------
struct ConvArgs { const float4* src[9]; };
#define CQ_QKV (SZ_QKV / 4)
#define CQ_OUT (SZ_OUT / 4)
#define CQ_W1  (SZ_W1 / 4)
#define CQ_W2  (SZ_W2 / 4)
#define CQ_PE  (SZ_PE / 4)
__constant__ int c_cum[10] = {
    0,
    CQ_QKV,
    CQ_QKV + CQ_OUT,
    CQ_QKV + CQ_OUT + CQ_W1,
    CQ_QKV + CQ_OUT + CQ_W1 + CQ_W2,
    CQ_QKV + CQ_OUT + CQ_W1 + CQ_W2 + CQ_QKV,
    CQ_QKV + CQ_OUT + CQ_W1 + CQ_W2 + CQ_QKV + CQ_OUT,
    CQ_QKV + CQ_OUT + CQ_W1 + CQ_W2 + CQ_QKV + CQ_OUT + CQ_W1,
    CQ_QKV + CQ_OUT + CQ_W1 + CQ_W2 + CQ_QKV + CQ_OUT + CQ_W1 + CQ_W2,
    CQ_QKV + CQ_OUT + CQ_W1 + CQ_W2 + CQ_QKV + CQ_OUT + CQ_W1 + CQ_W2 + CQ_PE
};
__constant__ int c_dst[9] = { OFF_EQKV / 4, OFF_EOUT / 4, OFF_EW1 / 4, OFF_EW2 / 4,
                              OFF_DQKV / 4, OFF_DOUT / 4, OFF_DW1 / 4, OFF_DW2 / 4,
                              OFF_PE / 4 };
__global__ void conv_all_kernel(ConvArgs args, __nv_bfloat162* __restrict__ dstbase, int total) {
    for (int i = blockIdx.x * blockDim.x + threadIdx.x; i < total; i += gridDim.x * blockDim.x) {
        int reg = 0;
#pragma unroll
        for (int r = 1; r < 9; r++) if (i >= c_cum[r]) reg = r;
        int loc = i - c_cum[reg];
        float4 v = args.src[reg][loc];
        __nv_bfloat162* d = dstbase + (size_t)(c_dst[reg] + loc) * 2;
        d[0] = __floats2bfloat162_rn(v.x, v.y);
        d[1] = __floats2bfloat162_rn(v.z, v.w);
    }
}
__global__ void conv_pad_kernel(const float* __restrict__ src, __nv_bfloat16* __restrict__ dst) {
    int i = blockIdx.x * blockDim.x + threadIdx.x;
    if (i >= DM * 128) return;
    int r = i >> 7, c = i & 127;
    dst[i] = __float2bfloat16((c < ZZ) ? src[r * ZZ + c] : 0.f);
}

// ---------------- warp-MMA GEMM: 128x128x64 block, 2-slot pipeline, 1 sync / 64-K ----------------
#define MM_SMEM (2 * (128 * 72 + 128 * 72) * 2)   // 73728 bytes

template <int MODE>
__global__ void __launch_bounds__(256, 2) mm_kernel(
    const __nv_bfloat16* __restrict__ A, long long sAi,
    const __nv_bfloat16* __restrict__ B, long long sBi,
    const float* __restrict__ bias,
    __nv_bfloat16* __restrict__ C, long long sCi,
    int Nreal, int Kdim)
{
    int Mreal = g_Ntot * LL;
    int m0 = blockIdx.y * 128;
    if (m0 >= Mreal) return;
    int n0 = blockIdx.x * 128;
    size_t stA = (size_t)sAi, stB = (size_t)sBi;
    int Ktiles = Kdim >> 6;

    extern __shared__ __nv_bfloat16 sm[];
    __nv_bfloat16* As = sm;                    // [2][128][72]
    __nv_bfloat16* Bs = sm + 2 * 128 * 72;     // [2][128][72]

    int tid = threadIdx.x;
    int lane = tid & 31;
    int w = tid >> 5;
    int wm = w >> 1;
    int wn = w & 1;

    float acc[2][8][4];
#pragma unroll
    for (int i = 0; i < 2; i++)
#pragma unroll
        for (int j = 0; j < 8; j++)
#pragma unroll
            for (int q = 0; q < 4; q++) acc[i][j][q] = 0.f;

    auto load_tile = [&](int kt, int s) {
        __nv_bfloat16* as = As + s * 128 * 72;
        __nv_bfloat16* bs = Bs + s * 128 * 72;
#pragma unroll
        for (int i = 0; i < 4; i++) {
            int c = tid + i * 256;
            int r = c >> 3, ko = (c & 7) * 8;
            int m = imin(m0 + r, Mreal - 1);
            cp16(smem_u32(&as[r * 72 + ko]), A + (size_t)m * stA + (size_t)kt * 64 + ko);
        }
#pragma unroll
        for (int i = 0; i < 4; i++) {
            int c = tid + i * 256;
            int r = c >> 3, ko = (c & 7) * 8;
            int n = imin(n0 + r, Nreal - 1);
            cp16(smem_u32(&bs[r * 72 + ko]), B + (size_t)n * stB + (size_t)kt * 64 + ko);
        }
    };

    load_tile(0, 0);
    cp_commit();

    for (int kt = 0; kt < Ktiles; kt++) {
        cp_wait0();
        __syncthreads();
        if (kt + 1 < Ktiles) {
            load_tile(kt + 1, (kt + 1) & 1);
            cp_commit();
        }
        int s = kt & 1;
        const __nv_bfloat16* as = As + s * 128 * 72;
        const __nv_bfloat16* bs = Bs + s * 128 * 72;
#pragma unroll
        for (int ks = 0; ks < 4; ks++) {
            int k0 = ks * 16;
            uint32_t a[2][4], bb[8][2];
#pragma unroll
            for (int mf = 0; mf < 2; mf++) {
                int row = wm * 32 + mf * 16 + (lane & 7) + ((lane >> 3) & 1) * 8;
                int col = k0 + (lane >> 4) * 8;
                ldmx4(a[mf][0], a[mf][1], a[mf][2], a[mf][3], smem_u32(&as[row * 72 + col]));
            }
#pragma unroll
            for (int ng = 0; ng < 4; ng++) {
                int row = wn * 64 + ng * 16 + (lane & 7) + (lane >> 4) * 8;
                int col = k0 + ((lane >> 3) & 1) * 8;
                uint32_t r0, r1, r2, r3;
                ldmx4(r0, r1, r2, r3, smem_u32(&bs[row * 72 + col]));
                bb[ng * 2][0] = r0;     bb[ng * 2][1] = r1;
                bb[ng * 2 + 1][0] = r2; bb[ng * 2 + 1][1] = r3;
            }
#pragma unroll
            for (int mf = 0; mf < 2; mf++)
#pragma unroll
                for (int nf = 0; nf < 8; nf++)
                    mma16816(acc[mf][nf], a[mf], bb[nf]);
        }
    }

    int width = (int)sCi;
#pragma unroll
    for (int mf = 0; mf < 2; mf++) {
#pragma unroll
        for (int nf = 0; nf < 8; nf++) {
            int rbase = m0 + wm * 32 + mf * 16 + (lane >> 2);
            int cbase = n0 + wn * 64 + nf * 8 + (lane & 3) * 2;
            if (cbase >= width) continue;
#pragma unroll
            for (int q = 0; q < 2; q++) {
                int m = rbase + q * 8;
                if (m >= Mreal) continue;
                float v0 = (cbase < Nreal)     ? acc[mf][nf][q * 2]     + bias[cbase]     : 0.f;
                float v1 = (cbase + 1 < Nreal) ? acc[mf][nf][q * 2 + 1] + bias[cbase + 1] : 0.f;
                if (MODE == 1) { v0 = fmaxf(v0, 0.f); v1 = fmaxf(v1, 0.f); }
                if (MODE == 2) { v0 = tanhf(v0); v1 = tanhf(v1); }
                *(__nv_bfloat162*)(C + (size_t)m * width + cbase) = __floats2bfloat162_rn(v0, v1);
            }
        }
    }
}

// ---------------- flash attention (unchanged from R11 passing version) ----------------
#define FA_Q   0
#define FA_K   (128 * 72 * 2)
#define FA_V   (FA_K + 2 * 64 * 72 * 2)
#define FA_MSK (FA_V + 2 * 64 * 72 * 2)
#define FA_SMEM (FA_MSK + 512 * 4)

__global__ void __launch_bounds__(256) attn_kernel(
    const __nv_bfloat16* __restrict__ QKV, __nv_bfloat16* __restrict__ ATT)
{
    int Nt = g_Ntot;
    int n0 = blockIdx.x * 128;
    if (n0 >= Nt) return;
    int z = blockIdx.y;
    int l = z / HH, h = z % HH;
    int Mtiles = (Nt + 63) >> 6;

    extern __shared__ char smem[];
    __nv_bfloat16* Qs = (__nv_bfloat16*)(smem + FA_Q);
    __nv_bfloat16* Ks = (__nv_bfloat16*)(smem + FA_K);
    __nv_bfloat16* Vs = (__nv_bfloat16*)(smem + FA_V);
    float*        msk = (float*)(smem + FA_MSK);

    int tid = threadIdx.x;
    int lane = tid & 31;
    int w = tid >> 5;

    for (int j = tid; j < 512; j += 256)
        msk[j] = (j < Nt) ? g_MSK[j * LL + l] : -1e30f;

#pragma unroll
    for (int i = 0; i < 4; i++) {
        int c = tid + i * 256;
        int r = c >> 3, co = (c & 7) * 8;
        int n = imin(n0 + r, Nt - 1);
        cp16(smem_u32(&Qs[r * 72 + co]), QKV + ((size_t)n * LL + l) * (3 * DM) + h * HD + co);
    }
    cp_commit();

    auto load_kv = [&](int mt, int buf) {
#pragma unroll
        for (int i = 0; i < 2; i++) {
            int c = tid + i * 256;
            int r = c >> 3, co = (c & 7) * 8;
            int m = imin(mt * 64 + r, Nt - 1);
            const __nv_bfloat16* base = QKV + ((size_t)m * LL + l) * (3 * DM) + h * HD + co;
            cp16(smem_u32(&Ks[(buf * 64 + r) * 72 + co]), base + DM);
            cp16(smem_u32(&Vs[(buf * 64 + r) * 72 + co]), base + 2 * DM);
        }
    };

    load_kv(0, 0);
    cp_commit();
    cp_wait1();
    __syncthreads();

    uint32_t aq[4][4];
#pragma unroll
    for (int ks = 0; ks < 4; ks++) {
        int row = w * 16 + (lane & 7) + ((lane >> 3) & 1) * 8;
        int col = ks * 16 + (lane >> 4) * 8;
        ldmx4(aq[ks][0], aq[ks][1], aq[ks][2], aq[ks][3], smem_u32(&Qs[row * 72 + col]));
    }

    float oacc[8][4];
#pragma unroll
    for (int j = 0; j < 8; j++)
#pragma unroll
        for (int q = 0; q < 4; q++) oacc[j][q] = 0.f;
    float mrow[2] = { -1e30f, -1e30f };
    float lrow[2] = { 0.f, 0.f };

    for (int mt = 0; mt < Mtiles; mt++) {
        int buf = mt & 1;
        if (mt + 1 < Mtiles) { load_kv(mt + 1, buf ^ 1); cp_commit(); cp_wait1(); }
        else cp_wait0();
        __syncthreads();

        float sacc[8][4];
#pragma unroll
        for (int j = 0; j < 8; j++)
#pragma unroll
            for (int q = 0; q < 4; q++) sacc[j][q] = 0.f;

#pragma unroll
        for (int ks = 0; ks < 4; ks++) {
            uint32_t bb[8][2];
#pragma unroll
            for (int ng = 0; ng < 4; ng++) {
                int row = ng * 16 + (lane & 7) + (lane >> 4) * 8;
                int col = ks * 16 + ((lane >> 3) & 1) * 8;
                uint32_t r0, r1, r2, r3;
                ldmx4(r0, r1, r2, r3, smem_u32(&Ks[(buf * 64 + row) * 72 + col]));
                bb[ng * 2][0] = r0;     bb[ng * 2][1] = r1;
                bb[ng * 2 + 1][0] = r2; bb[ng * 2 + 1][1] = r3;
            }
#pragma unroll
            for (int nf = 0; nf < 8; nf++) mma16816(sacc[nf], aq[ks], bb[nf]);
        }

#pragma unroll
        for (int nf = 0; nf < 8; nf++) {
            int kc = mt * 64 + nf * 8 + (lane & 3) * 2;
            float mk0 = msk[kc], mk1 = msk[kc + 1];
            sacc[nf][0] = sacc[nf][0] * 0.125f + mk0;
            sacc[nf][1] = sacc[nf][1] * 0.125f + mk1;
            sacc[nf][2] = sacc[nf][2] * 0.125f + mk0;
            sacc[nf][3] = sacc[nf][3] * 0.125f + mk1;
        }

#pragma unroll
        for (int q = 0; q < 2; q++) {
            float tm = -1e30f;
#pragma unroll
            for (int nf = 0; nf < 8; nf++)
                tm = fmaxf(tm, fmaxf(sacc[nf][q * 2], sacc[nf][q * 2 + 1]));
            tm = fmaxf(tm, __shfl_xor_sync(0xffffffff, tm, 1));
            tm = fmaxf(tm, __shfl_xor_sync(0xffffffff, tm, 2));
            float mnew = fmaxf(mrow[q], tm);
            float sc = fexp(mrow[q] - mnew);
            float tsum = 0.f;
#pragma unroll
            for (int nf = 0; nf < 8; nf++) {
                float p0 = fexp(sacc[nf][q * 2]     - mnew);
                float p1 = fexp(sacc[nf][q * 2 + 1] - mnew);
                sacc[nf][q * 2] = p0; sacc[nf][q * 2 + 1] = p1;
                tsum += p0 + p1;
            }
            tsum += __shfl_xor_sync(0xffffffff, tsum, 1);
            tsum += __shfl_xor_sync(0xffffffff, tsum, 2);
            lrow[q] = lrow[q] * sc + tsum;
            mrow[q] = mnew;
#pragma unroll
            for (int nf = 0; nf < 8; nf++) {
                oacc[nf][q * 2]     *= sc;
                oacc[nf][q * 2 + 1] *= sc;
            }
        }

#pragma unroll
        for (int ks = 0; ks < 4; ks++) {
            uint32_t ap[4];
            ap[0] = packbf(sacc[2 * ks][0],     sacc[2 * ks][1]);
            ap[1] = packbf(sacc[2 * ks][2],     sacc[2 * ks][3]);
            ap[2] = packbf(sacc[2 * ks + 1][0], sacc[2 * ks + 1][1]);
            ap[3] = packbf(sacc[2 * ks + 1][2], sacc[2 * ks + 1][3]);
            uint32_t vb[8][2];
#pragma unroll
            for (int ng = 0; ng < 4; ng++) {
                int vrow = ks * 16 + (lane & 7) + ((lane >> 3) & 1) * 8;
                int vcol = ng * 16 + (lane >> 4) * 8;
                uint32_t r0, r1, r2, r3;
                ldmx4t(r0, r1, r2, r3, smem_u32(&Vs[(buf * 64 + vrow) * 72 + vcol]));
                vb[ng * 2][0] = r0;     vb[ng * 2][1] = r1;
                vb[ng * 2 + 1][0] = r2; vb[ng * 2 + 1][1] = r3;
            }
#pragma unroll
            for (int nf = 0; nf < 8; nf++) mma16816(oacc[nf], ap, vb[nf]);
        }
        __syncthreads();
    }

    float inv0 = 1.f / lrow[0];
    float inv1 = 1.f / lrow[1];
#pragma unroll
    for (int nf = 0; nf < 8; nf++) {
        int c = nf * 8 + (lane & 3) * 2;
#pragma unroll
        for (int q = 0; q < 2; q++) {
            int n = n0 + w * 16 + (lane >> 2) + q * 8;
            if (n < Nt) {
                float inv = q ? inv1 : inv0;
                __nv_bfloat16* row = ATT + ((size_t)n * LL + l) * DM + h * HD + c;
                *(__nv_bfloat162*)row =
                    __floats2bfloat162_rn(oacc[nf][q * 2] * inv, oacc[nf][q * 2 + 1] * inv);
            }
        }
    }
}

// ---------------- residual + LayerNorm: warp per row ----------------
__global__ void __launch_bounds__(256) add_ln_kernel(
    __nv_bfloat16* __restrict__ X, const __nv_bfloat16* __restrict__ Yv,
    const float* __restrict__ g, const float* __restrict__ b) {
    int row = blockIdx.x * 8 + (threadIdx.x >> 5);
    if (row >= g_Ntot * LL) return;
    int lane = threadIdx.x & 31;
    __nv_bfloat16* x = X + (size_t)row * DM;
    const __nv_bfloat16* y = Yv + (size_t)row * DM;

    float v[24];
    float s = 0.f, s2 = 0.f;
#pragma unroll
    for (int i = 0; i < 3; i++) {
        int d = i * 256 + lane * 8;
        uint4 xv = *(const uint4*)(x + d);
        uint4 yv = *(const uint4*)(y + d);
        const __nv_bfloat162* xp = (const __nv_bfloat162*)&xv;
        const __nv_bfloat162* yp = (const __nv_bfloat162*)&yv;
#pragma unroll
        for (int j = 0; j < 4; j++) {
            float2 xf = __bfloat1622float2(xp[j]);
            float2 yf = __bfloat1622float2(yp[j]);
            float u0 = xf.x + yf.x, u1 = xf.y + yf.y;
            v[i * 8 + j * 2] = u0; v[i * 8 + j * 2 + 1] = u1;
            s += u0 + u1; s2 += u0 * u0 + u1 * u1;
        }
    }
#pragma unroll
    for (int o = 16; o > 0; o >>= 1) {
        s  += __shfl_xor_sync(0xffffffff, s, o);
        s2 += __shfl_xor_sync(0xffffffff, s2, o);
    }
    float mean = s * (1.f / (float)DM);
    float var = s2 * (1.f / (float)DM) - mean * mean;
    float inv = rsqrtf(var + 1e-5f);
#pragma unroll
    for (int i = 0; i < 3; i++) {
        int d = i * 256 + lane * 8;
        float4 g0 = *(const float4*)(g + d);
        float4 g1 = *(const float4*)(g + d + 4);
        float4 b0 = *(const float4*)(b + d);
        float4 b1 = *(const float4*)(b + d + 4);
        uint4 ov;
        uint32_t* op = (uint32_t*)&ov;
        const float* gp0 = (const float*)&g0;
        const float* gp1 = (const float*)&g1;
        const float* bp0 = (const float*)&b0;
        const float* bp1 = (const float*)&b1;
#pragma unroll
        for (int j = 0; j < 2; j++) {
            float r0 = (v[i * 8 + j * 2]     - mean) * inv * gp0[j * 2]     + bp0[j * 2];
            float r1 = (v[i * 8 + j * 2 + 1] - mean) * inv * gp0[j * 2 + 1] + bp0[j * 2 + 1];
            op[j] = packbf(r0, r1);
        }
#pragma unroll
        for (int j = 0; j < 2; j++) {
            float r0 = (v[i * 8 + 4 + j * 2]     - mean) * inv * gp1[j * 2]     + bp1[j * 2];
            float r1 = (v[i * 8 + 4 + j * 2 + 1] - mean) * inv * gp1[j * 2 + 1] + bp1[j * 2 + 1];
            op[2 + j] = packbf(r0, r1);
        }
        *(uint4*)(x + d) = ov;
    }
}

// ---------------- anomaly ----------------
__global__ void anomaly_kernel() {
    int n = blockIdx.x;
    if (n >= g_Ntot) return;
    int t = threadIdx.x;
    float acc = 0.f;
#pragma unroll
    for (int i = 0; i < 3; i++) {
        int d = t + 256 * i;
        float m = 0.f;
        for (int l = 0; l < LL; l++)
            m += __bfloat162float(g_Xbf[((size_t)n * LL + l) * DM + d]);
        m *= (1.f / (float)LL);
        float diff = m - g_meanE[n * DM + d];
        acc += diff * diff;
    }
    __shared__ float red[256];
    red[t] = acc; __syncthreads();
    for (int s = 128; s > 0; s >>= 1) { if (t < s) red[t] += red[t + s]; __syncthreads(); }
    if (t == 0) g_s[n] = red[0];
}

// ---------------- selection ----------------
__global__ void select_kernel() {
    int b = threadIdx.x;
    if (b >= BB) return;
    int nr = g_nresp[b];
    int ne = g_next[b];
    bool used[TT];
    int ohf[TT];
#pragma unroll
    for (int j = 0; j < TT; j++) { used[j] = false; ohf[j] = 0; }
    ohf[0] = 1;
    g_nodefull[b * TT + 0] = 0;
    for (int i = 0; i < TT - 1; i++) {
        int node = 0;
        if (i < ne) {
            float best = INFINITY; int bj = 0;
            for (int j = 0; j < nr; j++) {
                if (!used[j] && g_s[j] < best) { best = g_s[j]; bj = j; }
            }
            used[bj] = true;
            node = bj + 1;
            ohf[node] = 1;
        }
        g_nodefull[b * TT + i + 1] = node;
    }
    for (int t = 0; t < TT; t++) g_oh[b * TT + t] = ohf[t];
}

// ---------------- merged output writer (oh, tl, sc, ext_mask, new_msk) ----------------
__global__ void outputs_kernel(const float* __restrict__ amask, float* __restrict__ out,
                               long long off_oh, long long off_em, long long off_sc,
                               long long off_tl, long long off_nm, int has_sc) {
    int bt = blockIdx.x;           // 512
    int t = threadIdx.x;           // 128
    int b = bt >> 5, tt = bt & 31;
    float ohv = (float)g_oh[bt];
    if (t < 64) {
        out[off_em + (size_t)bt * LL + t] = ohv;
    } else {
        int c = t - 64;
        int node = g_nodefull[bt];
        float valid = (tt == 0 || (tt - 1) < g_next[b]) ? 1.f : 0.f;
        out[off_nm + (size_t)bt * LL + c] =
            amask[((size_t)b * TT + node) * LL + c] * valid;
    }
    if (t == 0) out[off_oh + bt] = ohv;
    if (bt < BB && t == 1) out[off_tl + bt] = (float)(1 + g_next[bt]);
    if (bt == 16 && t == 2 && has_sc) out[off_sc] = 0.f;
}
__global__ void new_emb_kernel(const float* __restrict__ emb,
                               float* __restrict__ out, long long off) {
    int bt = blockIdx.x / 48;
    int r4 = (blockIdx.x % 48) * 256 + threadIdx.x;
    int b = bt >> 5;
    int node = g_nodefull[bt];
    float4 v = *(const float4*)(emb + ((size_t)b * TT + node) * (LL * DM) + (size_t)r4 * 4);
    float* dst = out + off + (size_t)bt * (LL * DM) + (size_t)r4 * 4;
    dst[0] = v.x; dst[1] = v.y; dst[2] = v.z; dst[3] = v.w;
}

// ---------------- host ----------------
static void run_layer(__nv_bfloat16* pW, int qkvOff, int outOff, int w1Off, int w2Off,
                      const float* qkvb, const float* outb,
                      const float* g1, const float* b1,
                      const float* c1, const float* c2,
                      const float* g2, const float* b2,
                      __nv_bfloat16* pX, __nv_bfloat16* pQKV, __nv_bfloat16* pATT,
                      __nv_bfloat16* pY, __nv_bfloat16* pHID) {
    const int GY = 248;
    const int LNB = (NMAX * LL + 7) / 8;
    mm_kernel<0><<<dim3(18, GY), 256, MM_SMEM>>>(pX, DM, pW + qkvOff, DM, qkvb, pQKV, 3 * DM, 3 * DM, DM);
    attn_kernel<<<dim3(4, 768), 256, FA_SMEM>>>(pQKV, pATT);
    mm_kernel<0><<<dim3(6, GY), 256, MM_SMEM>>>(pATT, DM, pW + outOff, DM, outb, pY, DM, DM, DM);
    add_ln_kernel<<<LNB, 256>>>(pX, pY, g1, b1);
    mm_kernel<1><<<dim3(16, GY), 256, MM_SMEM>>>(pX, DM, pW + w1Off, DM, c1, pHID, FF, FF, DM);
    mm_kernel<0><<<dim3(6, GY), 256, MM_SMEM>>>(pHID, FF, pW + w2Off, FF, c2, pY, DM, DM, FF);
    add_ln_kernel<<<LNB, 256>>>(pX, pY, g2, b2);
}

extern "C" void kernel_launch(void* const* d_in, const int* in_sizes, int n_in,
                              void* d_out, int out_size) {
    const int*   tree_lens = (const int*)d_in[0];
    const float* emb       = (const float*)d_in[1];
    const float* amask     = (const float*)d_in[2];
    const float* P[28];
    for (int i = 3; i < 31; i++) P[i - 3] = (const float*)d_in[i];
    float* out = (float*)d_out;

    __nv_bfloat16 *pX, *pQKV, *pATT, *pY, *pHID, *pZ, *pW;
    cudaGetSymbolAddress((void**)&pX, g_Xbf);
    cudaGetSymbolAddress((void**)&pQKV, g_QKVbf);
    cudaGetSymbolAddress((void**)&pATT, g_ATTbf);
    cudaGetSymbolAddress((void**)&pY, g_Ybf);
    cudaGetSymbolAddress((void**)&pHID, g_HIDbf);
    cudaGetSymbolAddress((void**)&pZ, g_Zbf);
    cudaGetSymbolAddress((void**)&pW, g_Wbf);

    cudaFuncSetAttribute(attn_kernel, cudaFuncAttributeMaxDynamicSharedMemorySize, FA_SMEM);
    cudaFuncSetAttribute(mm_kernel<0>, cudaFuncAttributeMaxDynamicSharedMemorySize, MM_SMEM);
    cudaFuncSetAttribute(mm_kernel<1>, cudaFuncAttributeMaxDynamicSharedMemorySize, MM_SMEM);
    cudaFuncSetAttribute(mm_kernel<2>, cudaFuncAttributeMaxDynamicSharedMemorySize, MM_SMEM);

    const long long NE_ELEMS = (long long)BB * TT * LL * DM;
    const long long TOT_W = 512 + 32768 + 1 + 16 + NE_ELEMS + 32768;
    int has_sc = ((long long)out_size == TOT_W - 1) ? 0 : 1;
    long long off_oh = 0;
    long long off_em = 512;
    long long off_sc = 512 + 32768;
    long long off_tl = off_sc + (has_sc ? 1 : 0);
    long long off_ne = off_tl + 16;
    long long off_nm = off_ne + NE_ELEMS;

    setup_kernel<<<1, 32>>>(tree_lens);
    gather_kernel<<<dim3(NMAX, LL), 192>>>(emb, amask);
    meanE_kernel<<<dim3(NMAX, 3), 256>>>(emb);

    ConvArgs ca;
    ca.src[0] = (const float4*)P[0];  ca.src[1] = (const float4*)P[2];
    ca.src[2] = (const float4*)P[6];  ca.src[3] = (const float4*)P[8];
    ca.src[4] = (const float4*)P[12]; ca.src[5] = (const float4*)P[14];
    ca.src[6] = (const float4*)P[18]; ca.src[7] = (const float4*)P[20];
    ca.src[8] = (const float4*)P[24];
    int conv_total = (CQ_QKV + CQ_OUT + CQ_W1 + CQ_W2) * 2 + CQ_PE;
    conv_all_kernel<<<2048, 256>>>(ca, (__nv_bfloat162*)pW, conv_total);
    conv_pad_kernel<<<(DM * 128 + 255) / 256, 256>>>(P[26], pW + OFF_PD);

    const int LQKV = 3 * DM * DM, LOUT = DM * DM, LW1 = FF * DM, LW2 = DM * FF;
    for (int i = 0; i < 2; i++)
        run_layer(pW, OFF_EQKV + i * LQKV, OFF_EOUT + i * LOUT,
                  OFF_EW1 + i * LW1, OFF_EW2 + i * LW2,
                  P[1] + (size_t)i * 3 * DM, P[3] + (size_t)i * DM,
                  P[4] + (size_t)i * DM, P[5] + (size_t)i * DM,
                  P[7] + (size_t)i * FF, P[9] + (size_t)i * DM,
                  P[10] + (size_t)i * DM, P[11] + (size_t)i * DM,
                  pX, pQKV, pATT, pY, pHID);

    mm_kernel<2><<<dim3(1, 248), 256, MM_SMEM>>>(pX, DM, pW + OFF_PE, DM, P[25], pZ, 128, ZZ, DM);
    mm_kernel<2><<<dim3(6, 248), 256, MM_SMEM>>>(pZ, 128, pW + OFF_PD, 128, P[27], pX, DM, DM, 128);

    for (int i = 0; i < 2; i++)
        run_layer(pW, OFF_DQKV + i * LQKV, OFF_DOUT + i * LOUT,
                  OFF_DW1 + i * LW1, OFF_DW2 + i * LW2,
                  P[13] + (size_t)i * 3 * DM, P[15] + (size_t)i * DM,
                  P[16] + (size_t)i * DM, P[17] + (size_t)i * DM,
                  P[19] + (size_t)i * FF, P[21] + (size_t)i * DM,
                  P[22] + (size_t)i * DM, P[23] + (size_t)i * DM,
                  pX, pQKV, pATT, pY, pHID);

    anomaly_kernel<<<NMAX, 256>>>();
    select_kernel<<<1, 32>>>();

    outputs_kernel<<<BB * TT, 128>>>(amask, out, off_oh, off_em, off_sc, off_tl, off_nm, has_sc);
    new_emb_kernel<<<BB * TT * 48, 256>>>(emb, out, off_ne);
}